// round 12
// baseline (speedup 1.0000x reference)
#include <cuda_runtime.h>
#include <math.h>

#define BB 4
#define CC 3
#define HH 1024
#define WW 1024
#define NBC 12          // B*C
#define G0 255
#define G1 127
#define G2 63
#define G3 31

typedef unsigned long long ull;

// ---------------- f32x2 helpers ----------------
__device__ __forceinline__ ull pack2(float lo, float hi) {
    ull r; asm("mov.b64 %0, {%1,%2};" : "=l"(r) : "f"(lo), "f"(hi)); return r;
}
__device__ __forceinline__ float2 unpack2(ull v) {
    float2 r; asm("mov.b64 {%0,%1}, %2;" : "=f"(r.x), "=f"(r.y) : "l"(v)); return r;
}
__device__ __forceinline__ ull fma2(ull a, ull b, ull c) {
    ull d; asm("fma.rn.f32x2 %0, %1, %2, %3;" : "=l"(d) : "l"(a), "l"(b), "l"(c)); return d;
}
__device__ __forceinline__ ull add2(ull a, ull b) {
    ull d; asm("add.rn.f32x2 %0, %1, %2;" : "=l"(d) : "l"(a), "l"(b)); return d;
}
__device__ __forceinline__ ull relu2(ull v) {
    float2 t = unpack2(v);
    return pack2(fmaxf(t.x, 0.f), fmaxf(t.y, 0.f));
}
__device__ __forceinline__ void cpa16(void* smem, const void* g) {
    unsigned int a = (unsigned int)__cvta_generic_to_shared(smem);
    asm volatile("cp.async.cg.shared.global [%0], [%1], 16;" :: "r"(a), "l"(g));
}

// ---------------- scratch ----------------
__device__ float dS0[4][NBC*G0*G0];   // level-0 box sums: Sg, Ss, Sgg, Sgs
__device__ float dF1[2][NBC*G1*G1];   // cov,var r=16
__device__ float dF2[2][NBC*G2*G2];   // r=32
__device__ float dF3[2][NBC*G3*G3];   // r=64
__device__ float dAf[NBC*G0*G0];      // A
__device__ float dCf[NBC*G0*G0];      // b = my1 - A*mx1

// ---------------- kernel 1: level-0 box sums, cp.async double-buffered ----------------
__global__ __launch_bounds__(256) void boxsum_kernel(const float* __restrict__ guide,
                                                     const float* __restrict__ src) {
    extern __shared__ __align__(16) float dyn[];
    float* bg[2] = {dyn, dyn + 4096};
    float* bs[2] = {dyn + 8192, dyn + 12288};

    const int t  = threadIdx.x;
    const int bc = blockIdx.y;
    const int i0 = blockIdx.x * 8;
    const int i1 = min(i0 + 8, 255);

    const float* gbase = guide + (size_t)bc * HH * WW;
    const float* sbase = src   + (size_t)bc * HH * WW;

    {
        const float* gp = gbase + (size_t)(4 * i0) * WW;
        const float* sp = sbase + (size_t)(4 * i0) * WW;
        #pragma unroll
        for (int k = 0; k < 4; ++k) {
            int idx = (t + k * 256) * 4;
            cpa16(bg[0] + idx, gp + idx);
            cpa16(bs[0] + idx, sp + idx);
        }
        asm volatile("cp.async.commit_group;");
    }

    float qg = 0.f, qs = 0.f, qgg = 0.f, qgs = 0.f;
    int s = 0;

    for (int m = i0; m <= i1; ++m) {
        if (m < i1) {
            const float* gp = gbase + (size_t)(4 * (m + 1)) * WW;
            const float* sp = sbase + (size_t)(4 * (m + 1)) * WW;
            #pragma unroll
            for (int k = 0; k < 4; ++k) {
                int idx = (t + k * 256) * 4;
                cpa16(bg[s ^ 1] + idx, gp + idx);
                cpa16(bs[s ^ 1] + idx, sp + idx);
            }
            asm volatile("cp.async.commit_group;");
            asm volatile("cp.async.wait_group 1;");
        } else {
            asm volatile("cp.async.wait_group 0;");
        }
        __syncthreads();

        if (t < 255) {
            float pg = 0.f, ps = 0.f, pgg = 0.f, pgs = 0.f;
            #pragma unroll
            for (int rr = 0; rr < 4; ++rr) {
                const float* g = bg[s] + rr * 1024 + 4 * t;
                const float* ss2 = bs[s] + rr * 1024 + 4 * t;
                float4 ga = *(const float4*)(g);
                float4 gb = *(const float4*)(g + 4);
                float4 sa = *(const float4*)(ss2);
                float4 sb = *(const float4*)(ss2 + 4);
                float gv[8] = {ga.x, ga.y, ga.z, ga.w, gb.x, gb.y, gb.z, gb.w};
                float sv[8] = {sa.x, sa.y, sa.z, sa.w, sb.x, sb.y, sb.z, sb.w};
                #pragma unroll
                for (int k = 0; k < 8; ++k) {
                    pg += gv[k];
                    ps += sv[k];
                    pgg = fmaf(gv[k], gv[k], pgg);
                    pgs = fmaf(gv[k], sv[k], pgs);
                }
            }
            if (m > i0) {
                int off = bc * G0 * G0 + (m - 1) * G0 + t;
                dS0[0][off] = qg + pg;
                dS0[1][off] = qs + ps;
                dS0[2][off] = qgg + pgg;
                dS0[3][off] = qgs + pgs;
            }
            qg = pg; qs = ps; qgg = pgg; qgs = pgs;
        }
        __syncthreads();
        s ^= 1;
    }
}

// ---------------- kernel 2: all pyramid levels directly from S0 ----------------
template<int T>
__device__ __forceinline__ void pyrL_direct(int bc, int i, int j, float INVN,
                                            float* fcov, float* fvar, int GOUT) {
    int p00 = bc * G0 * G0 + (T * i) * G0 + (T * j);
    float sg = 0.f, ss = 0.f, sgg = 0.f, sgs = 0.f;
    #pragma unroll
    for (int a = 0; a < T; ++a) {
        const float* r0 = &dS0[0][p00 + 2 * a * G0];
        const float* r1 = &dS0[1][p00 + 2 * a * G0];
        const float* r2 = &dS0[2][p00 + 2 * a * G0];
        const float* r3 = &dS0[3][p00 + 2 * a * G0];
        #pragma unroll
        for (int bb2 = 0; bb2 < T; ++bb2) {
            sg  += r0[2 * bb2];
            ss  += r1[2 * bb2];
            sgg += r2[2 * bb2];
            sgs += r3[2 * bb2];
        }
    }
    float mx = sg * INVN, my = ss * INVN;
    int o = bc * GOUT * GOUT + i * GOUT + j;
    fcov[o] = fmaf(-mx, my, sgs * INVN);
    fvar[o] = fmaf(-mx, mx, sgg * INVN);
}

#define NL1 (G1*G1)
#define NL2 (G2*G2)
#define NL3 (G3*G3)
#define NPYR (NL1 + NL2 + NL3)

__global__ __launch_bounds__(256) void pyr_all_kernel() {
    const int bc  = blockIdx.y;
    int idx = blockIdx.x * 256 + threadIdx.x;
    if (idx < NL1) {
        int i = idx / G1, j = idx - i * G1;
        int p00 = bc * G0 * G0 + 2 * i * G0 + 2 * j;
        float sg  = dS0[0][p00] + dS0[0][p00+2] + dS0[0][p00+2*G0] + dS0[0][p00+2*G0+2];
        float ss  = dS0[1][p00] + dS0[1][p00+2] + dS0[1][p00+2*G0] + dS0[1][p00+2*G0+2];
        float sgg = dS0[2][p00] + dS0[2][p00+2] + dS0[2][p00+2*G0] + dS0[2][p00+2*G0+2];
        float sgs = dS0[3][p00] + dS0[3][p00+2] + dS0[3][p00+2*G0] + dS0[3][p00+2*G0+2];
        float mx = sg * (1.f/256.f), my = ss * (1.f/256.f);
        int o = bc * G1 * G1 + idx;
        dF1[0][o] = fmaf(-mx, my, sgs * (1.f/256.f));
        dF1[1][o] = fmaf(-mx, mx, sgg * (1.f/256.f));
    } else if (idx < NL1 + NL2) {
        int k = idx - NL1;
        int i = k / G2, j = k - i * G2;
        pyrL_direct<4>(bc, i, j, 1.f/1024.f, dF2[0], dF2[1], G2);
    } else if (idx < NPYR) {
        int k = idx - NL1 - NL2;
        int i = k / G3, j = k - i * G3;
        pyrL_direct<8>(bc, i, j, 1.f/4096.f, dF3[0], dF3[1], G3);
    }
}

// ---------------- bilinear ----------------
__device__ __forceinline__ float bilin(const float* __restrict__ p, int base, int G,
                                       float wx, float wy) {
    float v00 = p[base],     v01 = p[base + 1];
    float v10 = p[base + G], v11 = p[base + G + 1];
    float v0 = v00 + wx * (v01 - v00);
    float v1 = v10 + wx * (v11 - v10);
    return v0 + wy * (v1 - v0);
}

__device__ __forceinline__ void sampleLevel(const float* __restrict__ covP,
                                            const float* __restrict__ varP,
                                            int G, int b, int i, int j, float* xo) {
    float scale = (float)((double)(G - 1) / 254.0);
    float py = i * scale, px = j * scale;
    int iy = (int)py; if (iy > G - 2) iy = G - 2;
    int ix = (int)px; if (ix > G - 2) ix = G - 2;
    float wy = py - iy, wx = px - ix;
    #pragma unroll
    for (int c = 0; c < 3; ++c) {
        int base = ((b * 3 + c) * G + iy) * G + ix;
        xo[c]     = bilin(covP, base, G, wx, wy);
        xo[3 + c] = bilin(varP, base, G, wx, wy);
    }
}

// ---------------- kernel 3: fused featbuild + tiled GEMM MLP, persistent over batches ----------------
// Grid: (G0) = 255 blocks, each loops b = 0..3. Weight prep runs ONCE per block.
// Tile = 256 pixels (row i, batch b) x 48 outputs; warp = 6 lane-uniform outputs.
// smem layout (bytes):
//   x_s   [24][260] f  @ 0       (24960)   (reused as layer-3 reduction buffer)
//   h_s   [48][260] f  @ 24960   (49920)
//   w1d   [24][48] ull @ 74880   (9216)
//   w2d   [48][48] ull @ 84096   (18432)
//   w3d   [3][48]  ull @ 102528  (1152)
//   b1d   [48]     ull @ 103680  (384)
//   b2d   [48]     ull @ 104064  (384)
#define GEMM_SMEM 104448
#define XS_STRIDE 260

__global__ __launch_bounds__(256, 2) void gemm_kernel(
    const float* __restrict__ w1, const float* __restrict__ g1, const float* __restrict__ b1,
    const float* __restrict__ rm1, const float* __restrict__ rv1,
    const float* __restrict__ w2, const float* __restrict__ g2, const float* __restrict__ b2,
    const float* __restrict__ rm2, const float* __restrict__ rv2,
    const float* __restrict__ w3) {

    extern __shared__ __align__(16) char smem_raw[];
    float* x_s = (float*)smem_raw;
    float* h_s = (float*)(smem_raw + 24960);
    ull* w1d = (ull*)(smem_raw + 74880);
    ull* w2d = (ull*)(smem_raw + 84096);
    ull* w3d = (ull*)(smem_raw + 102528);
    ull* b1d = (ull*)(smem_raw + 103680);
    ull* b2d = (ull*)(smem_raw + 104064);

    const int t = threadIdx.x;
    const int i = blockIdx.x;   // row
    const int warp = t >> 5;
    const int lane = t & 31;
    const int o0   = warp * 6;  // 6 outputs per warp, uniform across lanes

    // ---- weight prep (folded BN, duplicated), ONCE per block ----
    for (int e = t; e < 48 * 24; e += 256) {
        int o = e / 24, c = e - o * 24;
        float inv1 = g1[o] * rsqrtf(rv1[o] + 1e-5f);
        float w = w1[e] * inv1;
        w1d[c * 48 + o] = pack2(w, w);
    }
    for (int e = t; e < 48 * 48; e += 256) {
        int o = e / 48, c = e - o * 48;
        float inv2 = g2[o] * rsqrtf(rv2[o] + 1e-5f);
        float w = w2[e] * inv2;
        w2d[c * 48 + o] = pack2(w, w);
    }
    if (t < 48) {
        float inv1 = g1[t] * rsqrtf(rv1[t] + 1e-5f);
        float bb1 = fmaf(-rm1[t], inv1, b1[t]);
        b1d[t] = pack2(bb1, bb1);
        float inv2 = g2[t] * rsqrtf(rv2[t] + 1e-5f);
        float bb2 = fmaf(-rm2[t], inv2, b2[t]);
        b2d[t] = pack2(bb2, bb2);
        #pragma unroll
        for (int cc = 0; cc < 3; ++cc) {
            float w = w3[cc * 48 + t];
            w3d[cc * 48 + t] = pack2(w, w);
        }
    }

    #pragma unroll 1
    for (int b = 0; b < BB; ++b) {
        __syncthreads();   // previous tile's red reads done (and weight prep on b=0)

        // ---- feature build: thread t = pixel (i, j=t) ----
        {
            float x[24];
            if (t < 255) {
                const int j = t;
                #pragma unroll
                for (int c = 0; c < 3; ++c) {
                    int off = (b * 3 + c) * G0 * G0 + i * G0 + j;
                    float sg  = dS0[0][off] * (1.f/64.f);
                    float ss  = dS0[1][off] * (1.f/64.f);
                    float sgg = dS0[2][off] * (1.f/64.f);
                    float sgs = dS0[3][off] * (1.f/64.f);
                    x[c]     = fmaf(-sg, ss, sgs);
                    x[3 + c] = fmaf(-sg, sg, sgg);
                }
                sampleLevel(dF1[0], dF1[1], G1, b, i, j, &x[6]);
                sampleLevel(dF2[0], dF2[1], G2, b, i, j, &x[12]);
                sampleLevel(dF3[0], dF3[1], G3, b, i, j, &x[18]);
            } else {
                #pragma unroll
                for (int f = 0; f < 24; ++f) x[f] = 0.f;
            }
            #pragma unroll
            for (int f = 0; f < 24; ++f)
                x_s[f * XS_STRIDE + t] = x[f];
        }
        __syncthreads();

        // ---- layer 1: 24 -> 48 ----
        ull acc[24];
        #pragma unroll
        for (int k = 0; k < 6; ++k) {
            ull bias = b1d[o0 + k];
            acc[k*4+0] = bias; acc[k*4+1] = bias; acc[k*4+2] = bias; acc[k*4+3] = bias;
        }
        #pragma unroll
        for (int c = 0; c < 24; ++c) {
            const float* xr = &x_s[c * XS_STRIDE];
            ulonglong2 xa = *(const ulonglong2*)(xr + 4 * lane);
            ulonglong2 xb = *(const ulonglong2*)(xr + 4 * lane + 128);
            const ulonglong2* wr = (const ulonglong2*)&w1d[c * 48 + o0];
            ulonglong2 w01 = wr[0], w23 = wr[1], w45 = wr[2];
            ull wv[6] = {w01.x, w01.y, w23.x, w23.y, w45.x, w45.y};
            #pragma unroll
            for (int k = 0; k < 6; ++k) {
                acc[k*4+0] = fma2(wv[k], xa.x, acc[k*4+0]);
                acc[k*4+1] = fma2(wv[k], xa.y, acc[k*4+1]);
                acc[k*4+2] = fma2(wv[k], xb.x, acc[k*4+2]);
                acc[k*4+3] = fma2(wv[k], xb.y, acc[k*4+3]);
            }
        }
        #pragma unroll
        for (int k = 0; k < 6; ++k) {
            float* hr = &h_s[(o0 + k) * XS_STRIDE];
            ulonglong2 v0; v0.x = relu2(acc[k*4+0]); v0.y = relu2(acc[k*4+1]);
            ulonglong2 v1; v1.x = relu2(acc[k*4+2]); v1.y = relu2(acc[k*4+3]);
            *(ulonglong2*)(hr + 4 * lane)       = v0;
            *(ulonglong2*)(hr + 4 * lane + 128) = v1;
        }
        __syncthreads();

        // ---- layer 2: 48 -> 48 ----
        #pragma unroll
        for (int k = 0; k < 6; ++k) {
            ull bias = b2d[o0 + k];
            acc[k*4+0] = bias; acc[k*4+1] = bias; acc[k*4+2] = bias; acc[k*4+3] = bias;
        }
        #pragma unroll
        for (int c = 0; c < 48; ++c) {
            const float* xr = &h_s[c * XS_STRIDE];
            ulonglong2 xa = *(const ulonglong2*)(xr + 4 * lane);
            ulonglong2 xb = *(const ulonglong2*)(xr + 4 * lane + 128);
            const ulonglong2* wr = (const ulonglong2*)&w2d[c * 48 + o0];
            ulonglong2 w01 = wr[0], w23 = wr[1], w45 = wr[2];
            ull wv[6] = {w01.x, w01.y, w23.x, w23.y, w45.x, w45.y};
            #pragma unroll
            for (int k = 0; k < 6; ++k) {
                acc[k*4+0] = fma2(wv[k], xa.x, acc[k*4+0]);
                acc[k*4+1] = fma2(wv[k], xa.y, acc[k*4+1]);
                acc[k*4+2] = fma2(wv[k], xb.x, acc[k*4+2]);
                acc[k*4+3] = fma2(wv[k], xb.y, acc[k*4+3]);
            }
        }
        // ---- layer 3 folded ----
        ull a3[12];
        #pragma unroll
        for (int m = 0; m < 12; ++m) a3[m] = 0ull;
        #pragma unroll
        for (int k = 0; k < 6; ++k) {
            ull r0 = relu2(acc[k*4+0]);
            ull r1 = relu2(acc[k*4+1]);
            ull r2 = relu2(acc[k*4+2]);
            ull r3 = relu2(acc[k*4+3]);
            #pragma unroll
            for (int cc = 0; cc < 3; ++cc) {
                ull w = w3d[cc * 48 + o0 + k];
                a3[cc*4+0] = fma2(w, r0, a3[cc*4+0]);
                a3[cc*4+1] = fma2(w, r1, a3[cc*4+1]);
                a3[cc*4+2] = fma2(w, r2, a3[cc*4+2]);
                a3[cc*4+3] = fma2(w, r3, a3[cc*4+3]);
            }
        }

        // ---- cross-warp reduction via smem (reuse x_s) ----
        ull* red = (ull*)x_s;
        {
            ull* rw = red + warp * 384;
            #pragma unroll
            for (int cc = 0; cc < 3; ++cc) {
                ulonglong2 v0; v0.x = a3[cc*4+0]; v0.y = a3[cc*4+1];
                ulonglong2 v1; v1.x = a3[cc*4+2]; v1.y = a3[cc*4+3];
                *(ulonglong2*)&rw[cc * 128 + 2 * lane]      = v0;
                *(ulonglong2*)&rw[cc * 128 + 2 * lane + 64] = v1;
            }
        }
        __syncthreads();

        for (int item = t; item < 384; item += 256) {
            int cc = item >> 7;
            int p  = item & 127;
            ull s = red[item];
            #pragma unroll
            for (int w = 1; w < 8; ++w) s = add2(s, red[w * 384 + item]);
            float2 A = unpack2(s);
            int plane = (b * 3 + cc) * G0 * G0 + i * G0;
            int j0 = 2 * p;
            {
                float mx = dS0[0][plane + j0] * (1.f/64.f);
                float my = dS0[1][plane + j0] * (1.f/64.f);
                dAf[plane + j0] = A.x;
                dCf[plane + j0] = fmaf(-A.x, mx, my);
            }
            if (j0 + 1 < G0) {
                float mx = dS0[0][plane + j0 + 1] * (1.f/64.f);
                float my = dS0[1][plane + j0 + 1] * (1.f/64.f);
                dAf[plane + j0 + 1] = A.y;
                dCf[plane + j0 + 1] = fmaf(-A.y, mx, my);
            }
        }
    }
}

// ---------------- kernel 4: upsample A,b + affine (2 rows/block, float4 fused tables) ----------------
__global__ __launch_bounds__(256) void final_kernel(const float* __restrict__ guide,
                                                    float* __restrict__ out) {
    __shared__ float4 tb[2][256];      // (Aval, Adelta, Cval, Cdelta)
    const int y0 = blockIdx.x * 2;
    const int bc = blockIdx.y;
    const int t  = threadIdx.x;
    const float scale = (float)(254.0 / 1023.0);

    #pragma unroll
    for (int r = 0; r < 2; ++r) {
        int y = y0 + r;
        float py = y * scale;
        int iy = (int)py; if (iy > 253) iy = 253;
        float wy = py - iy;
        if (t < 255) {
            int tn = min(t + 1, 254);
            int b0 = bc * G0 * G0 + iy * G0;
            float a0 = dAf[b0 + t],  a1 = dAf[b0 + G0 + t];
            float av = a0 + wy * (a1 - a0);
            float a0n = dAf[b0 + tn], a1n = dAf[b0 + G0 + tn];
            float avn = a0n + wy * (a1n - a0n);
            float c0 = dCf[b0 + t],  c1 = dCf[b0 + G0 + t];
            float cv = c0 + wy * (c1 - c0);
            float c0n = dCf[b0 + tn], c1n = dCf[b0 + G0 + tn];
            float cvn = c0n + wy * (c1n - c0n);
            tb[r][t] = make_float4(av, avn - av, cv, cvn - cv);
        }
    }
    __syncthreads();

    size_t row0 = ((size_t)bc * HH + y0) * WW;
    float4 g0 = ((const float4*)(guide + row0))[t];
    float4 g1 = ((const float4*)(guide + row0 + WW))[t];

    int ix0 = (int)((4 * t) * scale);      // <= 253
    float4 q00 = tb[0][ix0], q01 = tb[0][ix0 + 1];
    float4 q10 = tb[1][ix0], q11 = tb[1][ix0 + 1];

    float gv0[4] = {g0.x, g0.y, g0.z, g0.w};
    float gv1[4] = {g1.x, g1.y, g1.z, g1.w};
    float rv0[4], rv1[4];
    #pragma unroll
    for (int k = 0; k < 4; ++k) {
        float pxf = (4 * t + k) * scale;
        int ixk = (int)pxf; if (ixk > 253) ixk = 253;
        float wx = pxf - ixk;
        bool first = (ixk == ix0);
        float4 qa = first ? q00 : q01;
        float4 qb = first ? q10 : q11;
        float A0 = fmaf(wx, qa.y, qa.x);
        float C0 = fmaf(wx, qa.w, qa.z);
        float A1 = fmaf(wx, qb.y, qb.x);
        float C1 = fmaf(wx, qb.w, qb.z);
        rv0[k] = fmaf(A0, gv0[k], C0);
        rv1[k] = fmaf(A1, gv1[k], C1);
    }
    float4 r0 = {rv0[0], rv0[1], rv0[2], rv0[3]};
    float4 r1 = {rv1[0], rv1[1], rv1[2], rv1[3]};
    ((float4*)(out + row0))[t] = r0;
    ((float4*)(out + row0 + WW))[t] = r1;
}

// ---------------- launch ----------------
extern "C" void kernel_launch(void* const* d_in, const int* in_sizes, int n_in,
                              void* d_out, int out_size) {
    const float* guide = (const float*)d_in[0];
    const float* src   = (const float*)d_in[1];
    const float* w1  = (const float*)d_in[2];
    const float* g1  = (const float*)d_in[3];
    const float* b1  = (const float*)d_in[4];
    const float* rm1 = (const float*)d_in[5];
    const float* rv1 = (const float*)d_in[6];
    const float* w2  = (const float*)d_in[7];
    const float* g2  = (const float*)d_in[8];
    const float* b2  = (const float*)d_in[9];
    const float* rm2 = (const float*)d_in[10];
    const float* rv2 = (const float*)d_in[11];
    const float* w3  = (const float*)d_in[12];
    float* out = (float*)d_out;

    cudaFuncSetAttribute(boxsum_kernel, cudaFuncAttributeMaxDynamicSharedMemorySize, 65536);
    cudaFuncSetAttribute(gemm_kernel, cudaFuncAttributeMaxDynamicSharedMemorySize, GEMM_SMEM);

    boxsum_kernel<<<dim3(32, NBC), 256, 65536>>>(guide, src);
    pyr_all_kernel<<<dim3((NPYR + 255) / 256, NBC), 256>>>();
    gemm_kernel<<<G0, 256, GEMM_SMEM>>>(w1, g1, b1, rm1, rv1, w2, g2, b2, rm2, rv2, w3);
    final_kernel<<<dim3(HH / 2, NBC), 256>>>(guide, out);
}

// round 13
// speedup vs baseline: 1.3544x; 1.3544x over previous
#include <cuda_runtime.h>
#include <math.h>

#define BB 4
#define CC 3
#define HH 1024
#define WW 1024
#define NBC 12          // B*C
#define G0 255
#define G1 127
#define G2 63
#define G3 31

typedef unsigned long long ull;

// ---------------- f32x2 helpers ----------------
__device__ __forceinline__ ull pack2(float lo, float hi) {
    ull r; asm("mov.b64 %0, {%1,%2};" : "=l"(r) : "f"(lo), "f"(hi)); return r;
}
__device__ __forceinline__ float2 unpack2(ull v) {
    float2 r; asm("mov.b64 {%0,%1}, %2;" : "=f"(r.x), "=f"(r.y) : "l"(v)); return r;
}
__device__ __forceinline__ ull fma2(ull a, ull b, ull c) {
    ull d; asm("fma.rn.f32x2 %0, %1, %2, %3;" : "=l"(d) : "l"(a), "l"(b), "l"(c)); return d;
}
__device__ __forceinline__ ull add2(ull a, ull b) {
    ull d; asm("add.rn.f32x2 %0, %1, %2;" : "=l"(d) : "l"(a), "l"(b)); return d;
}
__device__ __forceinline__ ull relu2(ull v) {
    float2 t = unpack2(v);
    return pack2(fmaxf(t.x, 0.f), fmaxf(t.y, 0.f));
}
__device__ __forceinline__ void cpa16(void* smem, const void* g) {
    unsigned int a = (unsigned int)__cvta_generic_to_shared(smem);
    asm volatile("cp.async.cg.shared.global [%0], [%1], 16;" :: "r"(a), "l"(g));
}

// ---------------- scratch ----------------
__device__ float dS0[4][NBC*G0*G0];   // level-0 box sums: Sg, Ss, Sgg, Sgs
__device__ float dF1[2][NBC*G1*G1];   // cov,var r=16
__device__ float dF2[2][NBC*G2*G2];   // r=32
__device__ float dF3[2][NBC*G3*G3];   // r=64
__device__ float dAf[NBC*G0*G0];      // A
__device__ float dCf[NBC*G0*G0];      // b = my1 - A*mx1

// ---------------- kernel 1: level-0 box sums, cp.async double-buffered ----------------
__global__ __launch_bounds__(256) void boxsum_kernel(const float* __restrict__ guide,
                                                     const float* __restrict__ src) {
    extern __shared__ __align__(16) float dyn[];
    float* bg[2] = {dyn, dyn + 4096};
    float* bs[2] = {dyn + 8192, dyn + 12288};

    const int t  = threadIdx.x;
    const int bc = blockIdx.y;
    const int i0 = blockIdx.x * 8;
    const int i1 = min(i0 + 8, 255);

    const float* gbase = guide + (size_t)bc * HH * WW;
    const float* sbase = src   + (size_t)bc * HH * WW;

    {
        const float* gp = gbase + (size_t)(4 * i0) * WW;
        const float* sp = sbase + (size_t)(4 * i0) * WW;
        #pragma unroll
        for (int k = 0; k < 4; ++k) {
            int idx = (t + k * 256) * 4;
            cpa16(bg[0] + idx, gp + idx);
            cpa16(bs[0] + idx, sp + idx);
        }
        asm volatile("cp.async.commit_group;");
    }

    float qg = 0.f, qs = 0.f, qgg = 0.f, qgs = 0.f;
    int s = 0;

    for (int m = i0; m <= i1; ++m) {
        if (m < i1) {
            const float* gp = gbase + (size_t)(4 * (m + 1)) * WW;
            const float* sp = sbase + (size_t)(4 * (m + 1)) * WW;
            #pragma unroll
            for (int k = 0; k < 4; ++k) {
                int idx = (t + k * 256) * 4;
                cpa16(bg[s ^ 1] + idx, gp + idx);
                cpa16(bs[s ^ 1] + idx, sp + idx);
            }
            asm volatile("cp.async.commit_group;");
            asm volatile("cp.async.wait_group 1;");
        } else {
            asm volatile("cp.async.wait_group 0;");
        }
        __syncthreads();

        if (t < 255) {
            float pg = 0.f, ps = 0.f, pgg = 0.f, pgs = 0.f;
            #pragma unroll
            for (int rr = 0; rr < 4; ++rr) {
                const float* g = bg[s] + rr * 1024 + 4 * t;
                const float* ss2 = bs[s] + rr * 1024 + 4 * t;
                float4 ga = *(const float4*)(g);
                float4 gb = *(const float4*)(g + 4);
                float4 sa = *(const float4*)(ss2);
                float4 sb = *(const float4*)(ss2 + 4);
                float gv[8] = {ga.x, ga.y, ga.z, ga.w, gb.x, gb.y, gb.z, gb.w};
                float sv[8] = {sa.x, sa.y, sa.z, sa.w, sb.x, sb.y, sb.z, sb.w};
                #pragma unroll
                for (int k = 0; k < 8; ++k) {
                    pg += gv[k];
                    ps += sv[k];
                    pgg = fmaf(gv[k], gv[k], pgg);
                    pgs = fmaf(gv[k], sv[k], pgs);
                }
            }
            if (m > i0) {
                int off = bc * G0 * G0 + (m - 1) * G0 + t;
                dS0[0][off] = qg + pg;
                dS0[1][off] = qs + ps;
                dS0[2][off] = qgg + pgg;
                dS0[3][off] = qgs + pgs;
            }
            qg = pg; qs = ps; qgg = pgg; qgs = pgs;
        }
        __syncthreads();
        s ^= 1;
    }
}

// ---------------- kernel 2: all pyramid levels directly from S0 ----------------
template<int T>
__device__ __forceinline__ void pyrL_direct(int bc, int i, int j, float INVN,
                                            float* fcov, float* fvar, int GOUT) {
    int p00 = bc * G0 * G0 + (T * i) * G0 + (T * j);
    float sg = 0.f, ss = 0.f, sgg = 0.f, sgs = 0.f;
    #pragma unroll
    for (int a = 0; a < T; ++a) {
        const float* r0 = &dS0[0][p00 + 2 * a * G0];
        const float* r1 = &dS0[1][p00 + 2 * a * G0];
        const float* r2 = &dS0[2][p00 + 2 * a * G0];
        const float* r3 = &dS0[3][p00 + 2 * a * G0];
        #pragma unroll
        for (int bb2 = 0; bb2 < T; ++bb2) {
            sg  += r0[2 * bb2];
            ss  += r1[2 * bb2];
            sgg += r2[2 * bb2];
            sgs += r3[2 * bb2];
        }
    }
    float mx = sg * INVN, my = ss * INVN;
    int o = bc * GOUT * GOUT + i * GOUT + j;
    fcov[o] = fmaf(-mx, my, sgs * INVN);
    fvar[o] = fmaf(-mx, mx, sgg * INVN);
}

#define NL1 (G1*G1)
#define NL2 (G2*G2)
#define NL3 (G3*G3)
#define NPYR (NL1 + NL2 + NL3)

__global__ __launch_bounds__(256) void pyr_all_kernel() {
    const int bc  = blockIdx.y;
    int idx = blockIdx.x * 256 + threadIdx.x;
    if (idx < NL1) {
        int i = idx / G1, j = idx - i * G1;
        int p00 = bc * G0 * G0 + 2 * i * G0 + 2 * j;
        float sg  = dS0[0][p00] + dS0[0][p00+2] + dS0[0][p00+2*G0] + dS0[0][p00+2*G0+2];
        float ss  = dS0[1][p00] + dS0[1][p00+2] + dS0[1][p00+2*G0] + dS0[1][p00+2*G0+2];
        float sgg = dS0[2][p00] + dS0[2][p00+2] + dS0[2][p00+2*G0] + dS0[2][p00+2*G0+2];
        float sgs = dS0[3][p00] + dS0[3][p00+2] + dS0[3][p00+2*G0] + dS0[3][p00+2*G0+2];
        float mx = sg * (1.f/256.f), my = ss * (1.f/256.f);
        int o = bc * G1 * G1 + idx;
        dF1[0][o] = fmaf(-mx, my, sgs * (1.f/256.f));
        dF1[1][o] = fmaf(-mx, mx, sgg * (1.f/256.f));
    } else if (idx < NL1 + NL2) {
        int k = idx - NL1;
        int i = k / G2, j = k - i * G2;
        pyrL_direct<4>(bc, i, j, 1.f/1024.f, dF2[0], dF2[1], G2);
    } else if (idx < NPYR) {
        int k = idx - NL1 - NL2;
        int i = k / G3, j = k - i * G3;
        pyrL_direct<8>(bc, i, j, 1.f/4096.f, dF3[0], dF3[1], G3);
    }
}

// ---------------- bilinear ----------------
__device__ __forceinline__ float bilin(const float* __restrict__ p, int base, int G,
                                       float wx, float wy) {
    float v00 = p[base],     v01 = p[base + 1];
    float v10 = p[base + G], v11 = p[base + G + 1];
    float v0 = v00 + wx * (v01 - v00);
    float v1 = v10 + wx * (v11 - v10);
    return v0 + wy * (v1 - v0);
}

__device__ __forceinline__ void sampleLevel(const float* __restrict__ covP,
                                            const float* __restrict__ varP,
                                            int G, int b, int i, int j, float* xo) {
    float scale = (float)((double)(G - 1) / 254.0);
    float py = i * scale, px = j * scale;
    int iy = (int)py; if (iy > G - 2) iy = G - 2;
    int ix = (int)px; if (ix > G - 2) ix = G - 2;
    float wy = py - iy, wx = px - ix;
    #pragma unroll
    for (int c = 0; c < 3; ++c) {
        int base = ((b * 3 + c) * G + iy) * G + ix;
        xo[c]     = bilin(covP, base, G, wx, wy);
        xo[3 + c] = bilin(varP, base, G, wx, wy);
    }
}

// ---------------- kernel 3: fused featbuild + tiled GEMM MLP, 384 threads ----------------
// Grid (G0, BB); block = 384 threads (12 warps x 4 lane-uniform outputs),
// tile = 256 pixels x 48 outputs. Every warp spans all 128 pixel-pairs
// (4 pairs per lane), so weight loads stay broadcast and x loads stay LDS.128.
// smem layout (bytes):
//   x_s   [24][260] f  @ 0       (24960)
//   h_s   [48][260] f  @ 24960   (49920)   (tail reused as layer-3 reduction buffer)
//   w1d   [24][48] ull @ 74880   (9216)
//   w2d   [48][48] ull @ 84096   (18432)
//   w3d   [3][48]  ull @ 102528  (1152)
//   b1d   [48]     ull @ 103680  (384)
//   b2d   [48]     ull @ 104064  (384)
#define GEMM_SMEM 104448
#define XS_STRIDE 260
#define GT 384

__global__ __launch_bounds__(GT, 2) void gemm_kernel(
    const float* __restrict__ w1, const float* __restrict__ g1, const float* __restrict__ b1,
    const float* __restrict__ rm1, const float* __restrict__ rv1,
    const float* __restrict__ w2, const float* __restrict__ g2, const float* __restrict__ b2,
    const float* __restrict__ rm2, const float* __restrict__ rv2,
    const float* __restrict__ w3) {

    extern __shared__ __align__(16) char smem_raw[];
    float* x_s = (float*)smem_raw;
    float* h_s = (float*)(smem_raw + 24960);
    ull* red = (ull*)(smem_raw + 24960);      // overlaps h_s; used after layer-2 reads done
    ull* w1d = (ull*)(smem_raw + 74880);
    ull* w2d = (ull*)(smem_raw + 84096);
    ull* w3d = (ull*)(smem_raw + 102528);
    ull* b1d = (ull*)(smem_raw + 103680);
    ull* b2d = (ull*)(smem_raw + 104064);

    const int t = threadIdx.x;
    const int i = blockIdx.x;   // row
    const int b = blockIdx.y;   // batch

    // ---- weight prep (folded BN, duplicated), spread over all 384 threads ----
    for (int e = t; e < 48 * 24; e += GT) {
        int o = e / 24, c = e - o * 24;
        float inv1 = g1[o] * rsqrtf(rv1[o] + 1e-5f);
        float w = w1[e] * inv1;
        w1d[c * 48 + o] = pack2(w, w);
    }
    for (int e = t; e < 48 * 48; e += GT) {
        int o = e / 48, c = e - o * 48;
        float inv2 = g2[o] * rsqrtf(rv2[o] + 1e-5f);
        float w = w2[e] * inv2;
        w2d[c * 48 + o] = pack2(w, w);
    }
    if (t < 48) {
        float inv1 = g1[t] * rsqrtf(rv1[t] + 1e-5f);
        float bb1 = fmaf(-rm1[t], inv1, b1[t]);
        b1d[t] = pack2(bb1, bb1);
        float inv2 = g2[t] * rsqrtf(rv2[t] + 1e-5f);
        float bb2 = fmaf(-rm2[t], inv2, b2[t]);
        b2d[t] = pack2(bb2, bb2);
        #pragma unroll
        for (int cc = 0; cc < 3; ++cc) {
            float w = w3[cc * 48 + t];
            w3d[cc * 48 + t] = pack2(w, w);
        }
    }

    // ---- feature build: threads 0..255 -> pixel (i, j=t) ----
    if (t < 256) {
        float x[24];
        if (t < 255) {
            const int j = t;
            #pragma unroll
            for (int c = 0; c < 3; ++c) {
                int off = (b * 3 + c) * G0 * G0 + i * G0 + j;
                float sg  = dS0[0][off] * (1.f/64.f);
                float ss  = dS0[1][off] * (1.f/64.f);
                float sgg = dS0[2][off] * (1.f/64.f);
                float sgs = dS0[3][off] * (1.f/64.f);
                x[c]     = fmaf(-sg, ss, sgs);
                x[3 + c] = fmaf(-sg, sg, sgg);
            }
            sampleLevel(dF1[0], dF1[1], G1, b, i, j, &x[6]);
            sampleLevel(dF2[0], dF2[1], G2, b, i, j, &x[12]);
            sampleLevel(dF3[0], dF3[1], G3, b, i, j, &x[18]);
        } else {
            #pragma unroll
            for (int f = 0; f < 24; ++f) x[f] = 0.f;
        }
        #pragma unroll
        for (int f = 0; f < 24; ++f)
            x_s[f * XS_STRIDE + t] = x[f];
    }
    __syncthreads();

    const int warp = t >> 5;           // 0..11
    const int lane = t & 31;
    const int o0   = warp * 4;         // 4 outputs per warp, uniform across lanes

    // lane owns pairs {2l, 2l+1, 2l+64, 2l+65}

    // ---- layer 1: 24 -> 48 ----
    ull acc[16];                        // [k(out 0..3)][q(pair 0..3)]
    #pragma unroll
    for (int k = 0; k < 4; ++k) {
        ull bias = b1d[o0 + k];
        acc[k*4+0] = bias; acc[k*4+1] = bias; acc[k*4+2] = bias; acc[k*4+3] = bias;
    }
    #pragma unroll
    for (int c = 0; c < 24; ++c) {
        const float* xr = &x_s[c * XS_STRIDE];
        ulonglong2 xa = *(const ulonglong2*)(xr + 4 * lane);
        ulonglong2 xb = *(const ulonglong2*)(xr + 4 * lane + 128);
        const ulonglong2* wr = (const ulonglong2*)&w1d[c * 48 + o0];
        ulonglong2 w01 = wr[0], w23 = wr[1];
        ull wv[4] = {w01.x, w01.y, w23.x, w23.y};
        #pragma unroll
        for (int k = 0; k < 4; ++k) {
            acc[k*4+0] = fma2(wv[k], xa.x, acc[k*4+0]);
            acc[k*4+1] = fma2(wv[k], xa.y, acc[k*4+1]);
            acc[k*4+2] = fma2(wv[k], xb.x, acc[k*4+2]);
            acc[k*4+3] = fma2(wv[k], xb.y, acc[k*4+3]);
        }
    }
    // relu + store h (STS.128, conflict-free)
    #pragma unroll
    for (int k = 0; k < 4; ++k) {
        float* hr = &h_s[(o0 + k) * XS_STRIDE];
        ulonglong2 v0; v0.x = relu2(acc[k*4+0]); v0.y = relu2(acc[k*4+1]);
        ulonglong2 v1; v1.x = relu2(acc[k*4+2]); v1.y = relu2(acc[k*4+3]);
        *(ulonglong2*)(hr + 4 * lane)       = v0;
        *(ulonglong2*)(hr + 4 * lane + 128) = v1;
    }
    __syncthreads();

    // ---- layer 2: 48 -> 48 ----
    #pragma unroll
    for (int k = 0; k < 4; ++k) {
        ull bias = b2d[o0 + k];
        acc[k*4+0] = bias; acc[k*4+1] = bias; acc[k*4+2] = bias; acc[k*4+3] = bias;
    }
    #pragma unroll
    for (int c = 0; c < 48; ++c) {
        const float* xr = &h_s[c * XS_STRIDE];
        ulonglong2 xa = *(const ulonglong2*)(xr + 4 * lane);
        ulonglong2 xb = *(const ulonglong2*)(xr + 4 * lane + 128);
        const ulonglong2* wr = (const ulonglong2*)&w2d[c * 48 + o0];
        ulonglong2 w01 = wr[0], w23 = wr[1];
        ull wv[4] = {w01.x, w01.y, w23.x, w23.y};
        #pragma unroll
        for (int k = 0; k < 4; ++k) {
            acc[k*4+0] = fma2(wv[k], xa.x, acc[k*4+0]);
            acc[k*4+1] = fma2(wv[k], xa.y, acc[k*4+1]);
            acc[k*4+2] = fma2(wv[k], xb.x, acc[k*4+2]);
            acc[k*4+3] = fma2(wv[k], xb.y, acc[k*4+3]);
        }
    }
    // ---- layer 3 folded: relu(h2) -> 3 partial accumulators over warp's 4 channels ----
    ull a3[12];                    // [cc][q]
    #pragma unroll
    for (int m = 0; m < 12; ++m) a3[m] = 0ull;
    #pragma unroll
    for (int k = 0; k < 4; ++k) {
        ull r0 = relu2(acc[k*4+0]);
        ull r1 = relu2(acc[k*4+1]);
        ull r2 = relu2(acc[k*4+2]);
        ull r3 = relu2(acc[k*4+3]);
        #pragma unroll
        for (int cc = 0; cc < 3; ++cc) {
            ull w = w3d[cc * 48 + o0 + k];     // uniform LDS.64
            a3[cc*4+0] = fma2(w, r0, a3[cc*4+0]);
            a3[cc*4+1] = fma2(w, r1, a3[cc*4+1]);
            a3[cc*4+2] = fma2(w, r2, a3[cc*4+2]);
            a3[cc*4+3] = fma2(w, r3, a3[cc*4+3]);
        }
    }

    // ---- cross-warp reduction: red overlaps h_s, so sync until all layer-2 reads done ----
    __syncthreads();
    {
        ull* rw = red + warp * 384;        // 12 * 384 ull = 36864 B <= 49920
        #pragma unroll
        for (int cc = 0; cc < 3; ++cc) {
            ulonglong2 v0; v0.x = a3[cc*4+0]; v0.y = a3[cc*4+1];
            ulonglong2 v1; v1.x = a3[cc*4+2]; v1.y = a3[cc*4+3];
            *(ulonglong2*)&rw[cc * 128 + 2 * lane]      = v0;
            *(ulonglong2*)&rw[cc * 128 + 2 * lane + 64] = v1;
        }
    }
    __syncthreads();

    // 384 items (3 cc x 128 pairs) over 384 threads
    {
        int cc = t >> 7;
        int p  = t & 127;
        ull s = red[t];
        #pragma unroll
        for (int w = 1; w < 12; ++w) s = add2(s, red[w * 384 + t]);
        float2 A = unpack2(s);
        int plane = (b * 3 + cc) * G0 * G0 + i * G0;
        int j0 = 2 * p;
        {
            float mx = dS0[0][plane + j0] * (1.f/64.f);
            float my = dS0[1][plane + j0] * (1.f/64.f);
            dAf[plane + j0] = A.x;
            dCf[plane + j0] = fmaf(-A.x, mx, my);
        }
        if (j0 + 1 < G0) {
            float mx = dS0[0][plane + j0 + 1] * (1.f/64.f);
            float my = dS0[1][plane + j0 + 1] * (1.f/64.f);
            dAf[plane + j0 + 1] = A.y;
            dCf[plane + j0 + 1] = fmaf(-A.y, mx, my);
        }
    }
}

// ---------------- kernel 4: upsample A,b + affine (round-7 simple version) ----------------
__global__ __launch_bounds__(256) void final_kernel(const float* __restrict__ guide,
                                                    float* __restrict__ out) {
    __shared__ float sA[256];
    __shared__ float sC[256];
    const int y  = blockIdx.x;
    const int bc = blockIdx.y;
    const int t  = threadIdx.x;
    const float scale = (float)(254.0 / 1023.0);

    float py = y * scale;
    int iy = (int)py; if (iy > 253) iy = 253;
    float wy = py - iy;

    if (t < 255) {
        int b0 = bc * G0 * G0 + iy * G0 + t;
        float a0 = dAf[b0], a1 = dAf[b0 + G0];
        sA[t] = a0 + wy * (a1 - a0);
        float c0 = dCf[b0], c1 = dCf[b0 + G0];
        sC[t] = c0 + wy * (c1 - c0);
    }
    __syncthreads();

    size_t rowoff = ((size_t)bc * HH + y) * WW;
    float4 g = ((const float4*)(guide + rowoff))[t];
    float gv[4] = {g.x, g.y, g.z, g.w};
    float rv[4];
    #pragma unroll
    for (int k = 0; k < 4; ++k) {
        int xpix = 4 * t + k;
        float px = xpix * scale;
        int ix = (int)px; if (ix > 253) ix = 253;
        float wx = px - ix;
        float Av = sA[ix] + wx * (sA[ix + 1] - sA[ix]);
        float Cv = sC[ix] + wx * (sC[ix + 1] - sC[ix]);
        rv[k] = fmaf(Av, gv[k], Cv);
    }
    float4 r = {rv[0], rv[1], rv[2], rv[3]};
    ((float4*)(out + rowoff))[t] = r;
}

// ---------------- launch ----------------
extern "C" void kernel_launch(void* const* d_in, const int* in_sizes, int n_in,
                              void* d_out, int out_size) {
    const float* guide = (const float*)d_in[0];
    const float* src   = (const float*)d_in[1];
    const float* w1  = (const float*)d_in[2];
    const float* g1  = (const float*)d_in[3];
    const float* b1  = (const float*)d_in[4];
    const float* rm1 = (const float*)d_in[5];
    const float* rv1 = (const float*)d_in[6];
    const float* w2  = (const float*)d_in[7];
    const float* g2  = (const float*)d_in[8];
    const float* b2  = (const float*)d_in[9];
    const float* rm2 = (const float*)d_in[10];
    const float* rv2 = (const float*)d_in[11];
    const float* w3  = (const float*)d_in[12];
    float* out = (float*)d_out;

    cudaFuncSetAttribute(boxsum_kernel, cudaFuncAttributeMaxDynamicSharedMemorySize, 65536);
    cudaFuncSetAttribute(gemm_kernel, cudaFuncAttributeMaxDynamicSharedMemorySize, GEMM_SMEM);

    boxsum_kernel<<<dim3(32, NBC), 256, 65536>>>(guide, src);
    pyr_all_kernel<<<dim3((NPYR + 255) / 256, NBC), 256>>>();
    gemm_kernel<<<dim3(G0, BB), GT, GEMM_SMEM>>>(w1, g1, b1, rm1, rv1, w2, g2, b2, rm2, rv2, w3);
    final_kernel<<<dim3(HH, NBC), 256>>>(guide, out);
}

// round 14
// speedup vs baseline: 1.3825x; 1.0207x over previous
#include <cuda_runtime.h>
#include <math.h>

#define BB 4
#define CC 3
#define HH 1024
#define WW 1024
#define NBC 12          // B*C
#define G0 255
#define G1 127
#define G2 63
#define G3 31

typedef unsigned long long ull;

// ---------------- f32x2 helpers ----------------
__device__ __forceinline__ ull pack2(float lo, float hi) {
    ull r; asm("mov.b64 %0, {%1,%2};" : "=l"(r) : "f"(lo), "f"(hi)); return r;
}
__device__ __forceinline__ float2 unpack2(ull v) {
    float2 r; asm("mov.b64 {%0,%1}, %2;" : "=f"(r.x), "=f"(r.y) : "l"(v)); return r;
}
__device__ __forceinline__ ull fma2(ull a, ull b, ull c) {
    ull d; asm("fma.rn.f32x2 %0, %1, %2, %3;" : "=l"(d) : "l"(a), "l"(b), "l"(c)); return d;
}
__device__ __forceinline__ ull add2(ull a, ull b) {
    ull d; asm("add.rn.f32x2 %0, %1, %2;" : "=l"(d) : "l"(a), "l"(b)); return d;
}
__device__ __forceinline__ ull relu2(ull v) {
    float2 t = unpack2(v);
    return pack2(fmaxf(t.x, 0.f), fmaxf(t.y, 0.f));
}
__device__ __forceinline__ void cpa16(void* smem, const void* g) {
    unsigned int a = (unsigned int)__cvta_generic_to_shared(smem);
    asm volatile("cp.async.cg.shared.global [%0], [%1], 16;" :: "r"(a), "l"(g));
}

// ---------------- scratch ----------------
__device__ float dS0[4][NBC*G0*G0];   // level-0 box sums: Sg, Ss, Sgg, Sgs
__device__ float dF1[2][NBC*G1*G1];   // cov,var r=16
__device__ float dF2[2][NBC*G2*G2];   // r=32
__device__ float dF3[2][NBC*G3*G3];   // r=64
__device__ float dAf[NBC*G0*G0];      // A
__device__ float dCf[NBC*G0*G0];      // b = my1 - A*mx1

// ---------------- kernel 1: level-0 box sums, cp.async double-buffered ----------------
__global__ __launch_bounds__(256) void boxsum_kernel(const float* __restrict__ guide,
                                                     const float* __restrict__ src) {
    extern __shared__ __align__(16) float dyn[];
    float* bg[2] = {dyn, dyn + 4096};
    float* bs[2] = {dyn + 8192, dyn + 12288};

    const int t  = threadIdx.x;
    const int bc = blockIdx.y;
    const int i0 = blockIdx.x * 8;
    const int i1 = min(i0 + 8, 255);

    const float* gbase = guide + (size_t)bc * HH * WW;
    const float* sbase = src   + (size_t)bc * HH * WW;

    {
        const float* gp = gbase + (size_t)(4 * i0) * WW;
        const float* sp = sbase + (size_t)(4 * i0) * WW;
        #pragma unroll
        for (int k = 0; k < 4; ++k) {
            int idx = (t + k * 256) * 4;
            cpa16(bg[0] + idx, gp + idx);
            cpa16(bs[0] + idx, sp + idx);
        }
        asm volatile("cp.async.commit_group;");
    }

    float qg = 0.f, qs = 0.f, qgg = 0.f, qgs = 0.f;
    int s = 0;

    for (int m = i0; m <= i1; ++m) {
        if (m < i1) {
            const float* gp = gbase + (size_t)(4 * (m + 1)) * WW;
            const float* sp = sbase + (size_t)(4 * (m + 1)) * WW;
            #pragma unroll
            for (int k = 0; k < 4; ++k) {
                int idx = (t + k * 256) * 4;
                cpa16(bg[s ^ 1] + idx, gp + idx);
                cpa16(bs[s ^ 1] + idx, sp + idx);
            }
            asm volatile("cp.async.commit_group;");
            asm volatile("cp.async.wait_group 1;");
        } else {
            asm volatile("cp.async.wait_group 0;");
        }
        __syncthreads();

        if (t < 255) {
            float pg = 0.f, ps = 0.f, pgg = 0.f, pgs = 0.f;
            #pragma unroll
            for (int rr = 0; rr < 4; ++rr) {
                const float* g = bg[s] + rr * 1024 + 4 * t;
                const float* ss2 = bs[s] + rr * 1024 + 4 * t;
                float4 ga = *(const float4*)(g);
                float4 gb = *(const float4*)(g + 4);
                float4 sa = *(const float4*)(ss2);
                float4 sb = *(const float4*)(ss2 + 4);
                float gv[8] = {ga.x, ga.y, ga.z, ga.w, gb.x, gb.y, gb.z, gb.w};
                float sv[8] = {sa.x, sa.y, sa.z, sa.w, sb.x, sb.y, sb.z, sb.w};
                #pragma unroll
                for (int k = 0; k < 8; ++k) {
                    pg += gv[k];
                    ps += sv[k];
                    pgg = fmaf(gv[k], gv[k], pgg);
                    pgs = fmaf(gv[k], sv[k], pgs);
                }
            }
            if (m > i0) {
                int off = bc * G0 * G0 + (m - 1) * G0 + t;
                dS0[0][off] = qg + pg;
                dS0[1][off] = qs + ps;
                dS0[2][off] = qgg + pgg;
                dS0[3][off] = qgs + pgs;
            }
            qg = pg; qs = ps; qgg = pgg; qgs = pgs;
        }
        __syncthreads();
        s ^= 1;
    }
}

// ---------------- kernel 2: all pyramid levels directly from S0 ----------------
template<int T>
__device__ __forceinline__ void pyrL_direct(int bc, int i, int j, float INVN,
                                            float* fcov, float* fvar, int GOUT) {
    int p00 = bc * G0 * G0 + (T * i) * G0 + (T * j);
    float sg = 0.f, ss = 0.f, sgg = 0.f, sgs = 0.f;
    #pragma unroll
    for (int a = 0; a < T; ++a) {
        const float* r0 = &dS0[0][p00 + 2 * a * G0];
        const float* r1 = &dS0[1][p00 + 2 * a * G0];
        const float* r2 = &dS0[2][p00 + 2 * a * G0];
        const float* r3 = &dS0[3][p00 + 2 * a * G0];
        #pragma unroll
        for (int bb2 = 0; bb2 < T; ++bb2) {
            sg  += r0[2 * bb2];
            ss  += r1[2 * bb2];
            sgg += r2[2 * bb2];
            sgs += r3[2 * bb2];
        }
    }
    float mx = sg * INVN, my = ss * INVN;
    int o = bc * GOUT * GOUT + i * GOUT + j;
    fcov[o] = fmaf(-mx, my, sgs * INVN);
    fvar[o] = fmaf(-mx, mx, sgg * INVN);
}

#define NL1 (G1*G1)
#define NL2 (G2*G2)
#define NL3 (G3*G3)
#define NPYR (NL1 + NL2 + NL3)

__global__ __launch_bounds__(256) void pyr_all_kernel() {
    const int bc  = blockIdx.y;
    int idx = blockIdx.x * 256 + threadIdx.x;
    if (idx < NL1) {
        int i = idx / G1, j = idx - i * G1;
        int p00 = bc * G0 * G0 + 2 * i * G0 + 2 * j;
        float sg  = dS0[0][p00] + dS0[0][p00+2] + dS0[0][p00+2*G0] + dS0[0][p00+2*G0+2];
        float ss  = dS0[1][p00] + dS0[1][p00+2] + dS0[1][p00+2*G0] + dS0[1][p00+2*G0+2];
        float sgg = dS0[2][p00] + dS0[2][p00+2] + dS0[2][p00+2*G0] + dS0[2][p00+2*G0+2];
        float sgs = dS0[3][p00] + dS0[3][p00+2] + dS0[3][p00+2*G0] + dS0[3][p00+2*G0+2];
        float mx = sg * (1.f/256.f), my = ss * (1.f/256.f);
        int o = bc * G1 * G1 + idx;
        dF1[0][o] = fmaf(-mx, my, sgs * (1.f/256.f));
        dF1[1][o] = fmaf(-mx, mx, sgg * (1.f/256.f));
    } else if (idx < NL1 + NL2) {
        int k = idx - NL1;
        int i = k / G2, j = k - i * G2;
        pyrL_direct<4>(bc, i, j, 1.f/1024.f, dF2[0], dF2[1], G2);
    } else if (idx < NPYR) {
        int k = idx - NL1 - NL2;
        int i = k / G3, j = k - i * G3;
        pyrL_direct<8>(bc, i, j, 1.f/4096.f, dF3[0], dF3[1], G3);
    }
}

// ---------------- bilinear ----------------
__device__ __forceinline__ float bilin(const float* __restrict__ p, int base, int G,
                                       float wx, float wy) {
    float v00 = p[base],     v01 = p[base + 1];
    float v10 = p[base + G], v11 = p[base + G + 1];
    float v0 = v00 + wx * (v01 - v00);
    float v1 = v10 + wx * (v11 - v10);
    return v0 + wy * (v1 - v0);
}

__device__ __forceinline__ void sampleLevel(const float* __restrict__ covP,
                                            const float* __restrict__ varP,
                                            int G, int b, int i, int j, float* xo) {
    float scale = (float)((double)(G - 1) / 254.0);
    float py = i * scale, px = j * scale;
    int iy = (int)py; if (iy > G - 2) iy = G - 2;
    int ix = (int)px; if (ix > G - 2) ix = G - 2;
    float wy = py - iy, wx = px - ix;
    #pragma unroll
    for (int c = 0; c < 3; ++c) {
        int base = ((b * 3 + c) * G + iy) * G + ix;
        xo[c]     = bilin(covP, base, G, wx, wy);
        xo[3 + c] = bilin(varP, base, G, wx, wy);
    }
}

// ---------------- kernel 3: fused featbuild + tiled GEMM MLP (256 thr, K-unroll x2) ----------------
// smem layout (bytes):
//   x_s   [24][260] f  @ 0       (24960)   (reused as layer-3 reduction buffer)
//   h_s   [48][260] f  @ 24960   (49920)
//   w1d   [24][48] ull @ 74880   (9216)
//   w2d   [48][48] ull @ 84096   (18432)
//   w3d   [3][48]  ull @ 102528  (1152)
//   b1d   [48]     ull @ 103680  (384)
//   b2d   [48]     ull @ 104064  (384)
#define GEMM_SMEM 104448
#define XS_STRIDE 260

__global__ __launch_bounds__(256, 2) void gemm_kernel(
    const float* __restrict__ w1, const float* __restrict__ g1, const float* __restrict__ b1,
    const float* __restrict__ rm1, const float* __restrict__ rv1,
    const float* __restrict__ w2, const float* __restrict__ g2, const float* __restrict__ b2,
    const float* __restrict__ rm2, const float* __restrict__ rv2,
    const float* __restrict__ w3) {

    extern __shared__ __align__(16) char smem_raw[];
    float* x_s = (float*)smem_raw;
    float* h_s = (float*)(smem_raw + 24960);
    ull* w1d = (ull*)(smem_raw + 74880);
    ull* w2d = (ull*)(smem_raw + 84096);
    ull* w3d = (ull*)(smem_raw + 102528);
    ull* b1d = (ull*)(smem_raw + 103680);
    ull* b2d = (ull*)(smem_raw + 104064);

    const int t = threadIdx.x;
    const int i = blockIdx.x;   // row
    const int b = blockIdx.y;   // batch

    // ---- weight prep (folded BN, duplicated), spread over all 256 threads ----
    for (int e = t; e < 48 * 24; e += 256) {
        int o = e / 24, c = e - o * 24;
        float inv1 = g1[o] * rsqrtf(rv1[o] + 1e-5f);
        float w = w1[e] * inv1;
        w1d[c * 48 + o] = pack2(w, w);
    }
    for (int e = t; e < 48 * 48; e += 256) {
        int o = e / 48, c = e - o * 48;
        float inv2 = g2[o] * rsqrtf(rv2[o] + 1e-5f);
        float w = w2[e] * inv2;
        w2d[c * 48 + o] = pack2(w, w);
    }
    if (t < 48) {
        float inv1 = g1[t] * rsqrtf(rv1[t] + 1e-5f);
        float bb1 = fmaf(-rm1[t], inv1, b1[t]);
        b1d[t] = pack2(bb1, bb1);
        float inv2 = g2[t] * rsqrtf(rv2[t] + 1e-5f);
        float bb2 = fmaf(-rm2[t], inv2, b2[t]);
        b2d[t] = pack2(bb2, bb2);
        #pragma unroll
        for (int cc = 0; cc < 3; ++cc) {
            float w = w3[cc * 48 + t];
            w3d[cc * 48 + t] = pack2(w, w);
        }
    }

    // ---- feature build: thread t = pixel (i, j=t) ----
    {
        float x[24];
        if (t < 255) {
            const int j = t;
            #pragma unroll
            for (int c = 0; c < 3; ++c) {
                int off = (b * 3 + c) * G0 * G0 + i * G0 + j;
                float sg  = dS0[0][off] * (1.f/64.f);
                float ss  = dS0[1][off] * (1.f/64.f);
                float sgg = dS0[2][off] * (1.f/64.f);
                float sgs = dS0[3][off] * (1.f/64.f);
                x[c]     = fmaf(-sg, ss, sgs);
                x[3 + c] = fmaf(-sg, sg, sgg);
            }
            sampleLevel(dF1[0], dF1[1], G1, b, i, j, &x[6]);
            sampleLevel(dF2[0], dF2[1], G2, b, i, j, &x[12]);
            sampleLevel(dF3[0], dF3[1], G3, b, i, j, &x[18]);
        } else {
            #pragma unroll
            for (int f = 0; f < 24; ++f) x[f] = 0.f;
        }
        #pragma unroll
        for (int f = 0; f < 24; ++f)
            x_s[f * XS_STRIDE + t] = x[f];
    }
    __syncthreads();

    const int warp = t >> 5;
    const int lane = t & 31;
    const int o0   = warp * 6;          // 6 outputs per warp, uniform across lanes

    // lane owns pairs {2l, 2l+1, 2l+64, 2l+65}

    // ---- layer 1: 24 -> 48, K-unrolled x2 with hoisted loads ----
    ull acc[24];
    #pragma unroll
    for (int k = 0; k < 6; ++k) {
        ull bias = b1d[o0 + k];
        acc[k*4+0] = bias; acc[k*4+1] = bias; acc[k*4+2] = bias; acc[k*4+3] = bias;
    }
    #pragma unroll
    for (int c = 0; c < 24; c += 2) {
        const float* xr0 = &x_s[c * XS_STRIDE];
        const float* xr1 = &x_s[(c + 1) * XS_STRIDE];
        ulonglong2 xa0 = *(const ulonglong2*)(xr0 + 4 * lane);
        ulonglong2 xb0 = *(const ulonglong2*)(xr0 + 4 * lane + 128);
        ulonglong2 xa1 = *(const ulonglong2*)(xr1 + 4 * lane);
        ulonglong2 xb1 = *(const ulonglong2*)(xr1 + 4 * lane + 128);
        const ulonglong2* wr0 = (const ulonglong2*)&w1d[c * 48 + o0];
        const ulonglong2* wr1 = (const ulonglong2*)&w1d[(c + 1) * 48 + o0];
        ulonglong2 wA0 = wr0[0], wB0 = wr0[1], wC0 = wr0[2];
        ulonglong2 wA1 = wr1[0], wB1 = wr1[1], wC1 = wr1[2];
        ull wv0[6] = {wA0.x, wA0.y, wB0.x, wB0.y, wC0.x, wC0.y};
        ull wv1[6] = {wA1.x, wA1.y, wB1.x, wB1.y, wC1.x, wC1.y};
        #pragma unroll
        for (int k = 0; k < 6; ++k) {
            acc[k*4+0] = fma2(wv0[k], xa0.x, acc[k*4+0]);
            acc[k*4+1] = fma2(wv0[k], xa0.y, acc[k*4+1]);
            acc[k*4+2] = fma2(wv0[k], xb0.x, acc[k*4+2]);
            acc[k*4+3] = fma2(wv0[k], xb0.y, acc[k*4+3]);
        }
        #pragma unroll
        for (int k = 0; k < 6; ++k) {
            acc[k*4+0] = fma2(wv1[k], xa1.x, acc[k*4+0]);
            acc[k*4+1] = fma2(wv1[k], xa1.y, acc[k*4+1]);
            acc[k*4+2] = fma2(wv1[k], xb1.x, acc[k*4+2]);
            acc[k*4+3] = fma2(wv1[k], xb1.y, acc[k*4+3]);
        }
    }
    // relu + store h (STS.128, conflict-free)
    #pragma unroll
    for (int k = 0; k < 6; ++k) {
        float* hr = &h_s[(o0 + k) * XS_STRIDE];
        ulonglong2 v0; v0.x = relu2(acc[k*4+0]); v0.y = relu2(acc[k*4+1]);
        ulonglong2 v1; v1.x = relu2(acc[k*4+2]); v1.y = relu2(acc[k*4+3]);
        *(ulonglong2*)(hr + 4 * lane)       = v0;
        *(ulonglong2*)(hr + 4 * lane + 128) = v1;
    }
    __syncthreads();

    // ---- layer 2: 48 -> 48, K-unrolled x2 with hoisted loads ----
    #pragma unroll
    for (int k = 0; k < 6; ++k) {
        ull bias = b2d[o0 + k];
        acc[k*4+0] = bias; acc[k*4+1] = bias; acc[k*4+2] = bias; acc[k*4+3] = bias;
    }
    #pragma unroll
    for (int c = 0; c < 48; c += 2) {
        const float* xr0 = &h_s[c * XS_STRIDE];
        const float* xr1 = &h_s[(c + 1) * XS_STRIDE];
        ulonglong2 xa0 = *(const ulonglong2*)(xr0 + 4 * lane);
        ulonglong2 xb0 = *(const ulonglong2*)(xr0 + 4 * lane + 128);
        ulonglong2 xa1 = *(const ulonglong2*)(xr1 + 4 * lane);
        ulonglong2 xb1 = *(const ulonglong2*)(xr1 + 4 * lane + 128);
        const ulonglong2* wr0 = (const ulonglong2*)&w2d[c * 48 + o0];
        const ulonglong2* wr1 = (const ulonglong2*)&w2d[(c + 1) * 48 + o0];
        ulonglong2 wA0 = wr0[0], wB0 = wr0[1], wC0 = wr0[2];
        ulonglong2 wA1 = wr1[0], wB1 = wr1[1], wC1 = wr1[2];
        ull wv0[6] = {wA0.x, wA0.y, wB0.x, wB0.y, wC0.x, wC0.y};
        ull wv1[6] = {wA1.x, wA1.y, wB1.x, wB1.y, wC1.x, wC1.y};
        #pragma unroll
        for (int k = 0; k < 6; ++k) {
            acc[k*4+0] = fma2(wv0[k], xa0.x, acc[k*4+0]);
            acc[k*4+1] = fma2(wv0[k], xa0.y, acc[k*4+1]);
            acc[k*4+2] = fma2(wv0[k], xb0.x, acc[k*4+2]);
            acc[k*4+3] = fma2(wv0[k], xb0.y, acc[k*4+3]);
        }
        #pragma unroll
        for (int k = 0; k < 6; ++k) {
            acc[k*4+0] = fma2(wv1[k], xa1.x, acc[k*4+0]);
            acc[k*4+1] = fma2(wv1[k], xa1.y, acc[k*4+1]);
            acc[k*4+2] = fma2(wv1[k], xb1.x, acc[k*4+2]);
            acc[k*4+3] = fma2(wv1[k], xb1.y, acc[k*4+3]);
        }
    }
    // ---- layer 3 folded ----
    ull a3[12];
    #pragma unroll
    for (int m = 0; m < 12; ++m) a3[m] = 0ull;
    #pragma unroll
    for (int k = 0; k < 6; ++k) {
        ull r0 = relu2(acc[k*4+0]);
        ull r1 = relu2(acc[k*4+1]);
        ull r2 = relu2(acc[k*4+2]);
        ull r3 = relu2(acc[k*4+3]);
        #pragma unroll
        for (int cc = 0; cc < 3; ++cc) {
            ull w = w3d[cc * 48 + o0 + k];
            a3[cc*4+0] = fma2(w, r0, a3[cc*4+0]);
            a3[cc*4+1] = fma2(w, r1, a3[cc*4+1]);
            a3[cc*4+2] = fma2(w, r2, a3[cc*4+2]);
            a3[cc*4+3] = fma2(w, r3, a3[cc*4+3]);
        }
    }

    // ---- cross-warp reduction via smem (reuse x_s) ----
    ull* red = (ull*)x_s;
    {
        ull* rw = red + warp * 384;
        #pragma unroll
        for (int cc = 0; cc < 3; ++cc) {
            ulonglong2 v0; v0.x = a3[cc*4+0]; v0.y = a3[cc*4+1];
            ulonglong2 v1; v1.x = a3[cc*4+2]; v1.y = a3[cc*4+3];
            *(ulonglong2*)&rw[cc * 128 + 2 * lane]      = v0;
            *(ulonglong2*)&rw[cc * 128 + 2 * lane + 64] = v1;
        }
    }
    __syncthreads();

    for (int item = t; item < 384; item += 256) {
        int cc = item >> 7;
        int p  = item & 127;
        ull s = red[item];
        #pragma unroll
        for (int w = 1; w < 8; ++w) s = add2(s, red[w * 384 + item]);
        float2 A = unpack2(s);
        int plane = (b * 3 + cc) * G0 * G0 + i * G0;
        int j0 = 2 * p;
        {
            float mx = dS0[0][plane + j0] * (1.f/64.f);
            float my = dS0[1][plane + j0] * (1.f/64.f);
            dAf[plane + j0] = A.x;
            dCf[plane + j0] = fmaf(-A.x, mx, my);
        }
        if (j0 + 1 < G0) {
            float mx = dS0[0][plane + j0 + 1] * (1.f/64.f);
            float my = dS0[1][plane + j0 + 1] * (1.f/64.f);
            dAf[plane + j0 + 1] = A.y;
            dCf[plane + j0 + 1] = fmaf(-A.y, mx, my);
        }
    }
}

// ---------------- kernel 4: upsample A,b + affine (simple 1-row) ----------------
__global__ __launch_bounds__(256) void final_kernel(const float* __restrict__ guide,
                                                    float* __restrict__ out) {
    __shared__ float sA[256];
    __shared__ float sC[256];
    const int y  = blockIdx.x;
    const int bc = blockIdx.y;
    const int t  = threadIdx.x;
    const float scale = (float)(254.0 / 1023.0);

    float py = y * scale;
    int iy = (int)py; if (iy > 253) iy = 253;
    float wy = py - iy;

    if (t < 255) {
        int b0 = bc * G0 * G0 + iy * G0 + t;
        float a0 = dAf[b0], a1 = dAf[b0 + G0];
        sA[t] = a0 + wy * (a1 - a0);
        float c0 = dCf[b0], c1 = dCf[b0 + G0];
        sC[t] = c0 + wy * (c1 - c0);
    }
    __syncthreads();

    size_t rowoff = ((size_t)bc * HH + y) * WW;
    float4 g = ((const float4*)(guide + rowoff))[t];
    float gv[4] = {g.x, g.y, g.z, g.w};
    float rv[4];
    #pragma unroll
    for (int k = 0; k < 4; ++k) {
        int xpix = 4 * t + k;
        float px = xpix * scale;
        int ix = (int)px; if (ix > 253) ix = 253;
        float wx = px - ix;
        float Av = sA[ix] + wx * (sA[ix + 1] - sA[ix]);
        float Cv = sC[ix] + wx * (sC[ix + 1] - sC[ix]);
        rv[k] = fmaf(Av, gv[k], Cv);
    }
    float4 r = {rv[0], rv[1], rv[2], rv[3]};
    ((float4*)(out + rowoff))[t] = r;
}

// ---------------- launch ----------------
extern "C" void kernel_launch(void* const* d_in, const int* in_sizes, int n_in,
                              void* d_out, int out_size) {
    const float* guide = (const float*)d_in[0];
    const float* src   = (const float*)d_in[1];
    const float* w1  = (const float*)d_in[2];
    const float* g1  = (const float*)d_in[3];
    const float* b1  = (const float*)d_in[4];
    const float* rm1 = (const float*)d_in[5];
    const float* rv1 = (const float*)d_in[6];
    const float* w2  = (const float*)d_in[7];
    const float* g2  = (const float*)d_in[8];
    const float* b2  = (const float*)d_in[9];
    const float* rm2 = (const float*)d_in[10];
    const float* rv2 = (const float*)d_in[11];
    const float* w3  = (const float*)d_in[12];
    float* out = (float*)d_out;

    cudaFuncSetAttribute(boxsum_kernel, cudaFuncAttributeMaxDynamicSharedMemorySize, 65536);
    cudaFuncSetAttribute(gemm_kernel, cudaFuncAttributeMaxDynamicSharedMemorySize, GEMM_SMEM);

    boxsum_kernel<<<dim3(32, NBC), 256, 65536>>>(guide, src);
    pyr_all_kernel<<<dim3((NPYR + 255) / 256, NBC), 256>>>();
    gemm_kernel<<<dim3(G0, BB), 256, GEMM_SMEM>>>(w1, g1, b1, rm1, rv1, w2, g2, b2, rm2, rv2, w3);
    final_kernel<<<dim3(HH, NBC), 256>>>(guide, out);
}

// round 15
// speedup vs baseline: 1.5110x; 1.0930x over previous
#include <cuda_runtime.h>
#include <math.h>

#define BB 4
#define CC 3
#define HH 1024
#define WW 1024
#define NBC 12          // B*C
#define G0 255
#define G1 127
#define G2 63
#define G3 31

typedef unsigned long long ull;

// ---------------- f32x2 helpers ----------------
__device__ __forceinline__ ull pack2(float lo, float hi) {
    ull r; asm("mov.b64 %0, {%1,%2};" : "=l"(r) : "f"(lo), "f"(hi)); return r;
}
__device__ __forceinline__ float2 unpack2(ull v) {
    float2 r; asm("mov.b64 {%0,%1}, %2;" : "=f"(r.x), "=f"(r.y) : "l"(v)); return r;
}
__device__ __forceinline__ ull fma2(ull a, ull b, ull c) {
    ull d; asm("fma.rn.f32x2 %0, %1, %2, %3;" : "=l"(d) : "l"(a), "l"(b), "l"(c)); return d;
}
__device__ __forceinline__ ull add2(ull a, ull b) {
    ull d; asm("add.rn.f32x2 %0, %1, %2;" : "=l"(d) : "l"(a), "l"(b)); return d;
}
__device__ __forceinline__ ull relu2(ull v) {
    float2 t = unpack2(v);
    return pack2(fmaxf(t.x, 0.f), fmaxf(t.y, 0.f));
}
__device__ __forceinline__ void cpa16(void* smem, const void* g) {
    unsigned int a = (unsigned int)__cvta_generic_to_shared(smem);
    asm volatile("cp.async.cg.shared.global [%0], [%1], 16;" :: "r"(a), "l"(g));
}

// ---------------- scratch ----------------
__device__ float dS0[4][NBC*G0*G0];   // level-0 box sums: Sg, Ss, Sgg, Sgs
__device__ float dF1[2][NBC*G1*G1];   // cov,var r=16
__device__ float dF2[2][NBC*G2*G2];   // r=32
__device__ float dF3[2][NBC*G3*G3];   // r=64
__device__ float dAf[NBC*G0*G0];      // A
__device__ float dCf[NBC*G0*G0];      // b = my1 - A*mx1

// ---------------- kernel 1: level-0 box sums, cp.async double-buffered ----------------
__global__ __launch_bounds__(256) void boxsum_kernel(const float* __restrict__ guide,
                                                     const float* __restrict__ src) {
    extern __shared__ __align__(16) float dyn[];
    float* bg[2] = {dyn, dyn + 4096};
    float* bs[2] = {dyn + 8192, dyn + 12288};

    const int t  = threadIdx.x;
    const int bc = blockIdx.y;
    const int i0 = blockIdx.x * 8;
    const int i1 = min(i0 + 8, 255);

    const float* gbase = guide + (size_t)bc * HH * WW;
    const float* sbase = src   + (size_t)bc * HH * WW;

    {
        const float* gp = gbase + (size_t)(4 * i0) * WW;
        const float* sp = sbase + (size_t)(4 * i0) * WW;
        #pragma unroll
        for (int k = 0; k < 4; ++k) {
            int idx = (t + k * 256) * 4;
            cpa16(bg[0] + idx, gp + idx);
            cpa16(bs[0] + idx, sp + idx);
        }
        asm volatile("cp.async.commit_group;");
    }

    float qg = 0.f, qs = 0.f, qgg = 0.f, qgs = 0.f;
    int s = 0;

    for (int m = i0; m <= i1; ++m) {
        if (m < i1) {
            const float* gp = gbase + (size_t)(4 * (m + 1)) * WW;
            const float* sp = sbase + (size_t)(4 * (m + 1)) * WW;
            #pragma unroll
            for (int k = 0; k < 4; ++k) {
                int idx = (t + k * 256) * 4;
                cpa16(bg[s ^ 1] + idx, gp + idx);
                cpa16(bs[s ^ 1] + idx, sp + idx);
            }
            asm volatile("cp.async.commit_group;");
            asm volatile("cp.async.wait_group 1;");
        } else {
            asm volatile("cp.async.wait_group 0;");
        }
        __syncthreads();

        if (t < 255) {
            float pg = 0.f, ps = 0.f, pgg = 0.f, pgs = 0.f;
            #pragma unroll
            for (int rr = 0; rr < 4; ++rr) {
                const float* g = bg[s] + rr * 1024 + 4 * t;
                const float* ss2 = bs[s] + rr * 1024 + 4 * t;
                float4 ga = *(const float4*)(g);
                float4 gb = *(const float4*)(g + 4);
                float4 sa = *(const float4*)(ss2);
                float4 sb = *(const float4*)(ss2 + 4);
                float gv[8] = {ga.x, ga.y, ga.z, ga.w, gb.x, gb.y, gb.z, gb.w};
                float sv[8] = {sa.x, sa.y, sa.z, sa.w, sb.x, sb.y, sb.z, sb.w};
                #pragma unroll
                for (int k = 0; k < 8; ++k) {
                    pg += gv[k];
                    ps += sv[k];
                    pgg = fmaf(gv[k], gv[k], pgg);
                    pgs = fmaf(gv[k], sv[k], pgs);
                }
            }
            if (m > i0) {
                int off = bc * G0 * G0 + (m - 1) * G0 + t;
                dS0[0][off] = qg + pg;
                dS0[1][off] = qs + ps;
                dS0[2][off] = qgg + pgg;
                dS0[3][off] = qgs + pgs;
            }
            qg = pg; qs = ps; qgg = pgg; qgs = pgs;
        }
        __syncthreads();
        s ^= 1;
    }
}

// ---------------- kernel 2: all pyramid levels directly from S0 ----------------
template<int T>
__device__ __forceinline__ void pyrL_direct(int bc, int i, int j, float INVN,
                                            float* fcov, float* fvar, int GOUT) {
    int p00 = bc * G0 * G0 + (T * i) * G0 + (T * j);
    float sg = 0.f, ss = 0.f, sgg = 0.f, sgs = 0.f;
    #pragma unroll
    for (int a = 0; a < T; ++a) {
        const float* r0 = &dS0[0][p00 + 2 * a * G0];
        const float* r1 = &dS0[1][p00 + 2 * a * G0];
        const float* r2 = &dS0[2][p00 + 2 * a * G0];
        const float* r3 = &dS0[3][p00 + 2 * a * G0];
        #pragma unroll
        for (int bb2 = 0; bb2 < T; ++bb2) {
            sg  += r0[2 * bb2];
            ss  += r1[2 * bb2];
            sgg += r2[2 * bb2];
            sgs += r3[2 * bb2];
        }
    }
    float mx = sg * INVN, my = ss * INVN;
    int o = bc * GOUT * GOUT + i * GOUT + j;
    fcov[o] = fmaf(-mx, my, sgs * INVN);
    fvar[o] = fmaf(-mx, mx, sgg * INVN);
}

#define NL1 (G1*G1)
#define NL2 (G2*G2)
#define NL3 (G3*G3)
#define NPYR (NL1 + NL2 + NL3)

__global__ __launch_bounds__(256) void pyr_all_kernel() {
    const int bc  = blockIdx.y;
    int idx = blockIdx.x * 256 + threadIdx.x;
    if (idx < NL1) {
        int i = idx / G1, j = idx - i * G1;
        int p00 = bc * G0 * G0 + 2 * i * G0 + 2 * j;
        float sg  = dS0[0][p00] + dS0[0][p00+2] + dS0[0][p00+2*G0] + dS0[0][p00+2*G0+2];
        float ss  = dS0[1][p00] + dS0[1][p00+2] + dS0[1][p00+2*G0] + dS0[1][p00+2*G0+2];
        float sgg = dS0[2][p00] + dS0[2][p00+2] + dS0[2][p00+2*G0] + dS0[2][p00+2*G0+2];
        float sgs = dS0[3][p00] + dS0[3][p00+2] + dS0[3][p00+2*G0] + dS0[3][p00+2*G0+2];
        float mx = sg * (1.f/256.f), my = ss * (1.f/256.f);
        int o = bc * G1 * G1 + idx;
        dF1[0][o] = fmaf(-mx, my, sgs * (1.f/256.f));
        dF1[1][o] = fmaf(-mx, mx, sgg * (1.f/256.f));
    } else if (idx < NL1 + NL2) {
        int k = idx - NL1;
        int i = k / G2, j = k - i * G2;
        pyrL_direct<4>(bc, i, j, 1.f/1024.f, dF2[0], dF2[1], G2);
    } else if (idx < NPYR) {
        int k = idx - NL1 - NL2;
        int i = k / G3, j = k - i * G3;
        pyrL_direct<8>(bc, i, j, 1.f/4096.f, dF3[0], dF3[1], G3);
    }
}

// ---------------- bilinear ----------------
__device__ __forceinline__ float bilin(const float* __restrict__ p, int base, int G,
                                       float wx, float wy) {
    float v00 = p[base],     v01 = p[base + 1];
    float v10 = p[base + G], v11 = p[base + G + 1];
    float v0 = v00 + wx * (v01 - v00);
    float v1 = v10 + wx * (v11 - v10);
    return v0 + wy * (v1 - v0);
}

__device__ __forceinline__ void sampleLevel(const float* __restrict__ covP,
                                            const float* __restrict__ varP,
                                            int G, int b, int i, int j, float* xo) {
    float scale = (float)((double)(G - 1) / 254.0);
    float py = i * scale, px = j * scale;
    int iy = (int)py; if (iy > G - 2) iy = G - 2;
    int ix = (int)px; if (ix > G - 2) ix = G - 2;
    float wy = py - iy, wx = px - ix;
    #pragma unroll
    for (int c = 0; c < 3; ++c) {
        int base = ((b * 3 + c) * G + iy) * G + ix;
        xo[c]     = bilin(covP, base, G, wx, wy);
        xo[3 + c] = bilin(varP, base, G, wx, wy);
    }
}

// ---------------- kernel 3: persistent fused featbuild + tiled GEMM MLP ----------------
// Grid = 296 = 2 x 148 blocks (exactly one wave at 2 blocks/SM, balanced by construction).
// Each block loops over tiles: tile = bid, bid+296, ... < 1020; tile -> (b, i).
// Weight prep runs ONCE per block. Body = round-9 measured-best inner loop.
// smem layout (bytes):
//   x_s   [24][260] f  @ 0       (24960)   (reused as layer-3 reduction buffer)
//   h_s   [48][260] f  @ 24960   (49920)
//   w1d   [24][48] ull @ 74880   (9216)
//   w2d   [48][48] ull @ 84096   (18432)
//   w3d   [3][48]  ull @ 102528  (1152)
//   b1d   [48]     ull @ 103680  (384)
//   b2d   [48]     ull @ 104064  (384)
#define GEMM_SMEM 104448
#define XS_STRIDE 260
#define GEMM_GRID 296
#define NTILES (G0 * BB)

__global__ __launch_bounds__(256, 2) void gemm_kernel(
    const float* __restrict__ w1, const float* __restrict__ g1, const float* __restrict__ b1,
    const float* __restrict__ rm1, const float* __restrict__ rv1,
    const float* __restrict__ w2, const float* __restrict__ g2, const float* __restrict__ b2,
    const float* __restrict__ rm2, const float* __restrict__ rv2,
    const float* __restrict__ w3) {

    extern __shared__ __align__(16) char smem_raw[];
    float* x_s = (float*)smem_raw;
    float* h_s = (float*)(smem_raw + 24960);
    ull* w1d = (ull*)(smem_raw + 74880);
    ull* w2d = (ull*)(smem_raw + 84096);
    ull* w3d = (ull*)(smem_raw + 102528);
    ull* b1d = (ull*)(smem_raw + 103680);
    ull* b2d = (ull*)(smem_raw + 104064);

    const int t = threadIdx.x;
    const int warp = t >> 5;
    const int lane = t & 31;
    const int o0   = warp * 6;          // 6 outputs per warp, uniform across lanes

    // ---- weight prep (folded BN, duplicated), ONCE per block ----
    for (int e = t; e < 48 * 24; e += 256) {
        int o = e / 24, c = e - o * 24;
        float inv1 = g1[o] * rsqrtf(rv1[o] + 1e-5f);
        float w = w1[e] * inv1;
        w1d[c * 48 + o] = pack2(w, w);
    }
    for (int e = t; e < 48 * 48; e += 256) {
        int o = e / 48, c = e - o * 48;
        float inv2 = g2[o] * rsqrtf(rv2[o] + 1e-5f);
        float w = w2[e] * inv2;
        w2d[c * 48 + o] = pack2(w, w);
    }
    if (t < 48) {
        float inv1 = g1[t] * rsqrtf(rv1[t] + 1e-5f);
        float bb1 = fmaf(-rm1[t], inv1, b1[t]);
        b1d[t] = pack2(bb1, bb1);
        float inv2 = g2[t] * rsqrtf(rv2[t] + 1e-5f);
        float bb2 = fmaf(-rm2[t], inv2, b2[t]);
        b2d[t] = pack2(bb2, bb2);
        #pragma unroll
        for (int cc = 0; cc < 3; ++cc) {
            float w = w3[cc * 48 + t];
            w3d[cc * 48 + t] = pack2(w, w);
        }
    }

    #pragma unroll 1
    for (int tile = blockIdx.x; tile < NTILES; tile += GEMM_GRID) {
        const int b = tile / G0;
        const int i = tile - b * G0;

        __syncthreads();   // previous tile's red reads done (and weight prep first time)

        // ---- feature build: thread t = pixel (i, j=t) ----
        {
            float x[24];
            if (t < 255) {
                const int j = t;
                #pragma unroll
                for (int c = 0; c < 3; ++c) {
                    int off = (b * 3 + c) * G0 * G0 + i * G0 + j;
                    float sg  = dS0[0][off] * (1.f/64.f);
                    float ss  = dS0[1][off] * (1.f/64.f);
                    float sgg = dS0[2][off] * (1.f/64.f);
                    float sgs = dS0[3][off] * (1.f/64.f);
                    x[c]     = fmaf(-sg, ss, sgs);
                    x[3 + c] = fmaf(-sg, sg, sgg);
                }
                sampleLevel(dF1[0], dF1[1], G1, b, i, j, &x[6]);
                sampleLevel(dF2[0], dF2[1], G2, b, i, j, &x[12]);
                sampleLevel(dF3[0], dF3[1], G3, b, i, j, &x[18]);
            } else {
                #pragma unroll
                for (int f = 0; f < 24; ++f) x[f] = 0.f;
            }
            #pragma unroll
            for (int f = 0; f < 24; ++f)
                x_s[f * XS_STRIDE + t] = x[f];
        }
        __syncthreads();

        // lane owns pairs {2l, 2l+1, 2l+64, 2l+65}

        // ---- layer 1: 24 -> 48 ----
        ull acc[24];
        #pragma unroll
        for (int k = 0; k < 6; ++k) {
            ull bias = b1d[o0 + k];
            acc[k*4+0] = bias; acc[k*4+1] = bias; acc[k*4+2] = bias; acc[k*4+3] = bias;
        }
        #pragma unroll
        for (int c = 0; c < 24; ++c) {
            const float* xr = &x_s[c * XS_STRIDE];
            ulonglong2 xa = *(const ulonglong2*)(xr + 4 * lane);
            ulonglong2 xb = *(const ulonglong2*)(xr + 4 * lane + 128);
            const ulonglong2* wr = (const ulonglong2*)&w1d[c * 48 + o0];
            ulonglong2 w01 = wr[0], w23 = wr[1], w45 = wr[2];
            ull wv[6] = {w01.x, w01.y, w23.x, w23.y, w45.x, w45.y};
            #pragma unroll
            for (int k = 0; k < 6; ++k) {
                acc[k*4+0] = fma2(wv[k], xa.x, acc[k*4+0]);
                acc[k*4+1] = fma2(wv[k], xa.y, acc[k*4+1]);
                acc[k*4+2] = fma2(wv[k], xb.x, acc[k*4+2]);
                acc[k*4+3] = fma2(wv[k], xb.y, acc[k*4+3]);
            }
        }
        #pragma unroll
        for (int k = 0; k < 6; ++k) {
            float* hr = &h_s[(o0 + k) * XS_STRIDE];
            ulonglong2 v0; v0.x = relu2(acc[k*4+0]); v0.y = relu2(acc[k*4+1]);
            ulonglong2 v1; v1.x = relu2(acc[k*4+2]); v1.y = relu2(acc[k*4+3]);
            *(ulonglong2*)(hr + 4 * lane)       = v0;
            *(ulonglong2*)(hr + 4 * lane + 128) = v1;
        }
        __syncthreads();

        // ---- layer 2: 48 -> 48 ----
        #pragma unroll
        for (int k = 0; k < 6; ++k) {
            ull bias = b2d[o0 + k];
            acc[k*4+0] = bias; acc[k*4+1] = bias; acc[k*4+2] = bias; acc[k*4+3] = bias;
        }
        #pragma unroll
        for (int c = 0; c < 48; ++c) {
            const float* xr = &h_s[c * XS_STRIDE];
            ulonglong2 xa = *(const ulonglong2*)(xr + 4 * lane);
            ulonglong2 xb = *(const ulonglong2*)(xr + 4 * lane + 128);
            const ulonglong2* wr = (const ulonglong2*)&w2d[c * 48 + o0];
            ulonglong2 w01 = wr[0], w23 = wr[1], w45 = wr[2];
            ull wv[6] = {w01.x, w01.y, w23.x, w23.y, w45.x, w45.y};
            #pragma unroll
            for (int k = 0; k < 6; ++k) {
                acc[k*4+0] = fma2(wv[k], xa.x, acc[k*4+0]);
                acc[k*4+1] = fma2(wv[k], xa.y, acc[k*4+1]);
                acc[k*4+2] = fma2(wv[k], xb.x, acc[k*4+2]);
                acc[k*4+3] = fma2(wv[k], xb.y, acc[k*4+3]);
            }
        }
        // ---- layer 3 folded ----
        ull a3[12];
        #pragma unroll
        for (int m = 0; m < 12; ++m) a3[m] = 0ull;
        #pragma unroll
        for (int k = 0; k < 6; ++k) {
            ull r0 = relu2(acc[k*4+0]);
            ull r1 = relu2(acc[k*4+1]);
            ull r2 = relu2(acc[k*4+2]);
            ull r3 = relu2(acc[k*4+3]);
            #pragma unroll
            for (int cc = 0; cc < 3; ++cc) {
                ull w = w3d[cc * 48 + o0 + k];
                a3[cc*4+0] = fma2(w, r0, a3[cc*4+0]);
                a3[cc*4+1] = fma2(w, r1, a3[cc*4+1]);
                a3[cc*4+2] = fma2(w, r2, a3[cc*4+2]);
                a3[cc*4+3] = fma2(w, r3, a3[cc*4+3]);
            }
        }

        // ---- cross-warp reduction via smem (reuse x_s) ----
        ull* red = (ull*)x_s;
        {
            ull* rw = red + warp * 384;
            #pragma unroll
            for (int cc = 0; cc < 3; ++cc) {
                ulonglong2 v0; v0.x = a3[cc*4+0]; v0.y = a3[cc*4+1];
                ulonglong2 v1; v1.x = a3[cc*4+2]; v1.y = a3[cc*4+3];
                *(ulonglong2*)&rw[cc * 128 + 2 * lane]      = v0;
                *(ulonglong2*)&rw[cc * 128 + 2 * lane + 64] = v1;
            }
        }
        __syncthreads();

        for (int item = t; item < 384; item += 256) {
            int cc = item >> 7;
            int p  = item & 127;
            ull s = red[item];
            #pragma unroll
            for (int w = 1; w < 8; ++w) s = add2(s, red[w * 384 + item]);
            float2 A = unpack2(s);
            int plane = (b * 3 + cc) * G0 * G0 + i * G0;
            int j0 = 2 * p;
            {
                float mx = dS0[0][plane + j0] * (1.f/64.f);
                float my = dS0[1][plane + j0] * (1.f/64.f);
                dAf[plane + j0] = A.x;
                dCf[plane + j0] = fmaf(-A.x, mx, my);
            }
            if (j0 + 1 < G0) {
                float mx = dS0[0][plane + j0 + 1] * (1.f/64.f);
                float my = dS0[1][plane + j0 + 1] * (1.f/64.f);
                dAf[plane + j0 + 1] = A.y;
                dCf[plane + j0 + 1] = fmaf(-A.y, mx, my);
            }
        }
    }
}

// ---------------- kernel 4: upsample A,b + affine (simple 1-row) ----------------
__global__ __launch_bounds__(256) void final_kernel(const float* __restrict__ guide,
                                                    float* __restrict__ out) {
    __shared__ float sA[256];
    __shared__ float sC[256];
    const int y  = blockIdx.x;
    const int bc = blockIdx.y;
    const int t  = threadIdx.x;
    const float scale = (float)(254.0 / 1023.0);

    float py = y * scale;
    int iy = (int)py; if (iy > 253) iy = 253;
    float wy = py - iy;

    if (t < 255) {
        int b0 = bc * G0 * G0 + iy * G0 + t;
        float a0 = dAf[b0], a1 = dAf[b0 + G0];
        sA[t] = a0 + wy * (a1 - a0);
        float c0 = dCf[b0], c1 = dCf[b0 + G0];
        sC[t] = c0 + wy * (c1 - c0);
    }
    __syncthreads();

    size_t rowoff = ((size_t)bc * HH + y) * WW;
    float4 g = ((const float4*)(guide + rowoff))[t];
    float gv[4] = {g.x, g.y, g.z, g.w};
    float rv[4];
    #pragma unroll
    for (int k = 0; k < 4; ++k) {
        int xpix = 4 * t + k;
        float px = xpix * scale;
        int ix = (int)px; if (ix > 253) ix = 253;
        float wx = px - ix;
        float Av = sA[ix] + wx * (sA[ix + 1] - sA[ix]);
        float Cv = sC[ix] + wx * (sC[ix + 1] - sC[ix]);
        rv[k] = fmaf(Av, gv[k], Cv);
    }
    float4 r = {rv[0], rv[1], rv[2], rv[3]};
    ((float4*)(out + rowoff))[t] = r;
}

// ---------------- launch ----------------
extern "C" void kernel_launch(void* const* d_in, const int* in_sizes, int n_in,
                              void* d_out, int out_size) {
    const float* guide = (const float*)d_in[0];
    const float* src   = (const float*)d_in[1];
    const float* w1  = (const float*)d_in[2];
    const float* g1  = (const float*)d_in[3];
    const float* b1  = (const float*)d_in[4];
    const float* rm1 = (const float*)d_in[5];
    const float* rv1 = (const float*)d_in[6];
    const float* w2  = (const float*)d_in[7];
    const float* g2  = (const float*)d_in[8];
    const float* b2  = (const float*)d_in[9];
    const float* rm2 = (const float*)d_in[10];
    const float* rv2 = (const float*)d_in[11];
    const float* w3  = (const float*)d_in[12];
    float* out = (float*)d_out;

    cudaFuncSetAttribute(boxsum_kernel, cudaFuncAttributeMaxDynamicSharedMemorySize, 65536);
    cudaFuncSetAttribute(gemm_kernel, cudaFuncAttributeMaxDynamicSharedMemorySize, GEMM_SMEM);

    boxsum_kernel<<<dim3(32, NBC), 256, 65536>>>(guide, src);
    pyr_all_kernel<<<dim3((NPYR + 255) / 256, NBC), 256>>>();
    gemm_kernel<<<GEMM_GRID, 256, GEMM_SMEM>>>(w1, g1, b1, rm1, rv1, w2, g2, b2, rm2, rv2, w3);
    final_kernel<<<dim3(HH, NBC), 256>>>(guide, out);
}

// round 16
// speedup vs baseline: 1.5195x; 1.0056x over previous
#include <cuda_runtime.h>
#include <math.h>

#define BB 4
#define CC 3
#define HH 1024
#define WW 1024
#define NBC 12          // B*C
#define G0 255
#define G1 127
#define G2 63
#define G3 31

typedef unsigned long long ull;

// ---------------- f32x2 helpers ----------------
__device__ __forceinline__ ull pack2(float lo, float hi) {
    ull r; asm("mov.b64 %0, {%1,%2};" : "=l"(r) : "f"(lo), "f"(hi)); return r;
}
__device__ __forceinline__ float2 unpack2(ull v) {
    float2 r; asm("mov.b64 {%0,%1}, %2;" : "=f"(r.x), "=f"(r.y) : "l"(v)); return r;
}
__device__ __forceinline__ ull fma2(ull a, ull b, ull c) {
    ull d; asm("fma.rn.f32x2 %0, %1, %2, %3;" : "=l"(d) : "l"(a), "l"(b), "l"(c)); return d;
}
__device__ __forceinline__ ull add2(ull a, ull b) {
    ull d; asm("add.rn.f32x2 %0, %1, %2;" : "=l"(d) : "l"(a), "l"(b)); return d;
}
__device__ __forceinline__ ull relu2(ull v) {
    float2 t = unpack2(v);
    return pack2(fmaxf(t.x, 0.f), fmaxf(t.y, 0.f));
}
__device__ __forceinline__ void cpa16(void* smem, const void* g) {
    unsigned int a = (unsigned int)__cvta_generic_to_shared(smem);
    asm volatile("cp.async.cg.shared.global [%0], [%1], 16;" :: "r"(a), "l"(g));
}

// ---------------- scratch ----------------
__device__ __align__(16) float4 dS4[NBC*G0*G0];   // (Sg, Ss, Sgg, Sgs) per level-0 cell
__device__ __align__(8)  float2 dF1v[NBC*G1*G1];  // (cov, var) r=16
__device__ __align__(8)  float2 dF2v[NBC*G2*G2];  // r=32
__device__ __align__(8)  float2 dF3v[NBC*G3*G3];  // r=64
__device__ float dAf[NBC*G0*G0];                  // A
__device__ float dCf[NBC*G0*G0];                  // b = my1 - A*mx1

// ---------------- kernel 1: level-0 box sums, cp.async double-buffered ----------------
__global__ __launch_bounds__(256) void boxsum_kernel(const float* __restrict__ guide,
                                                     const float* __restrict__ src) {
    extern __shared__ __align__(16) float dyn[];
    float* bg[2] = {dyn, dyn + 4096};
    float* bs[2] = {dyn + 8192, dyn + 12288};

    const int t  = threadIdx.x;
    const int bc = blockIdx.y;
    const int i0 = blockIdx.x * 8;
    const int i1 = min(i0 + 8, 255);

    const float* gbase = guide + (size_t)bc * HH * WW;
    const float* sbase = src   + (size_t)bc * HH * WW;

    {
        const float* gp = gbase + (size_t)(4 * i0) * WW;
        const float* sp = sbase + (size_t)(4 * i0) * WW;
        #pragma unroll
        for (int k = 0; k < 4; ++k) {
            int idx = (t + k * 256) * 4;
            cpa16(bg[0] + idx, gp + idx);
            cpa16(bs[0] + idx, sp + idx);
        }
        asm volatile("cp.async.commit_group;");
    }

    float qg = 0.f, qs = 0.f, qgg = 0.f, qgs = 0.f;
    int s = 0;

    for (int m = i0; m <= i1; ++m) {
        if (m < i1) {
            const float* gp = gbase + (size_t)(4 * (m + 1)) * WW;
            const float* sp = sbase + (size_t)(4 * (m + 1)) * WW;
            #pragma unroll
            for (int k = 0; k < 4; ++k) {
                int idx = (t + k * 256) * 4;
                cpa16(bg[s ^ 1] + idx, gp + idx);
                cpa16(bs[s ^ 1] + idx, sp + idx);
            }
            asm volatile("cp.async.commit_group;");
            asm volatile("cp.async.wait_group 1;");
        } else {
            asm volatile("cp.async.wait_group 0;");
        }
        __syncthreads();

        if (t < 255) {
            float pg = 0.f, ps = 0.f, pgg = 0.f, pgs = 0.f;
            #pragma unroll
            for (int rr = 0; rr < 4; ++rr) {
                const float* g = bg[s] + rr * 1024 + 4 * t;
                const float* ss2 = bs[s] + rr * 1024 + 4 * t;
                float4 ga = *(const float4*)(g);
                float4 gb = *(const float4*)(g + 4);
                float4 sa = *(const float4*)(ss2);
                float4 sb = *(const float4*)(ss2 + 4);
                float gv[8] = {ga.x, ga.y, ga.z, ga.w, gb.x, gb.y, gb.z, gb.w};
                float sv[8] = {sa.x, sa.y, sa.z, sa.w, sb.x, sb.y, sb.z, sb.w};
                #pragma unroll
                for (int k = 0; k < 8; ++k) {
                    pg += gv[k];
                    ps += sv[k];
                    pgg = fmaf(gv[k], gv[k], pgg);
                    pgs = fmaf(gv[k], sv[k], pgs);
                }
            }
            if (m > i0) {
                int off = bc * G0 * G0 + (m - 1) * G0 + t;
                float4 v;
                v.x = qg + pg;
                v.y = qs + ps;
                v.z = qgg + pgg;
                v.w = qgs + pgs;
                dS4[off] = v;                // one STG.128
            }
            qg = pg; qs = ps; qgg = pgg; qgs = pgs;
        }
        __syncthreads();
        s ^= 1;
    }
}

// ---------------- kernel 2: all pyramid levels directly from S0 (float4 loads) ----------------
template<int T>
__device__ __forceinline__ void pyrL_direct(int bc, int i, int j, float INVN,
                                            float2* fcv, int GOUT) {
    int p00 = bc * G0 * G0 + (T * i) * G0 + (T * j);
    float sg = 0.f, ss = 0.f, sgg = 0.f, sgs = 0.f;
    #pragma unroll
    for (int a = 0; a < T; ++a) {
        const float4* r = &dS4[p00 + 2 * a * G0];
        #pragma unroll
        for (int bb2 = 0; bb2 < T; ++bb2) {
            float4 v = r[2 * bb2];
            sg += v.x; ss += v.y; sgg += v.z; sgs += v.w;
        }
    }
    float mx = sg * INVN, my = ss * INVN;
    int o = bc * GOUT * GOUT + i * GOUT + j;
    float cov = fmaf(-mx, my, sgs * INVN);
    float var = fmaf(-mx, mx, sgg * INVN);
    fcv[o] = make_float2(cov, var);
}

#define NL1 (G1*G1)
#define NL2 (G2*G2)
#define NL3 (G3*G3)
#define NPYR (NL1 + NL2 + NL3)

__global__ __launch_bounds__(256) void pyr_all_kernel() {
    const int bc  = blockIdx.y;
    int idx = blockIdx.x * 256 + threadIdx.x;
    if (idx < NL1) {
        int i = idx / G1, j = idx - i * G1;
        int p00 = bc * G0 * G0 + 2 * i * G0 + 2 * j;
        float4 v00 = dS4[p00],          v01 = dS4[p00 + 2];
        float4 v10 = dS4[p00 + 2 * G0], v11 = dS4[p00 + 2 * G0 + 2];
        float sg  = v00.x + v01.x + v10.x + v11.x;
        float ss  = v00.y + v01.y + v10.y + v11.y;
        float sgg = v00.z + v01.z + v10.z + v11.z;
        float sgs = v00.w + v01.w + v10.w + v11.w;
        float mx = sg * (1.f/256.f), my = ss * (1.f/256.f);
        int o = bc * G1 * G1 + idx;
        float cov = fmaf(-mx, my, sgs * (1.f/256.f));
        float var = fmaf(-mx, mx, sgg * (1.f/256.f));
        dF1v[o] = make_float2(cov, var);
    } else if (idx < NL1 + NL2) {
        int k = idx - NL1;
        int i = k / G2, j = k - i * G2;
        pyrL_direct<4>(bc, i, j, 1.f/1024.f, dF2v, G2);
    } else if (idx < NPYR) {
        int k = idx - NL1 - NL2;
        int i = k / G3, j = k - i * G3;
        pyrL_direct<8>(bc, i, j, 1.f/4096.f, dF3v, G3);
    }
}

// ---------------- bilinear over (cov,var) pairs ----------------
__device__ __forceinline__ void sampleLevel2(const float2* __restrict__ cvP,
                                             int G, int b, int i, int j, float* xo) {
    float scale = (float)((double)(G - 1) / 254.0);
    float py = i * scale, px = j * scale;
    int iy = (int)py; if (iy > G - 2) iy = G - 2;
    int ix = (int)px; if (ix > G - 2) ix = G - 2;
    float wy = py - iy, wx = px - ix;
    #pragma unroll
    for (int c = 0; c < 3; ++c) {
        int base = ((b * 3 + c) * G + iy) * G + ix;
        float2 v00 = cvP[base],     v01 = cvP[base + 1];
        float2 v10 = cvP[base + G], v11 = cvP[base + G + 1];
        // cov
        {
            float a0 = v00.x + wx * (v01.x - v00.x);
            float a1 = v10.x + wx * (v11.x - v10.x);
            xo[c] = a0 + wy * (a1 - a0);
        }
        // var
        {
            float a0 = v00.y + wx * (v01.y - v00.y);
            float a1 = v10.y + wx * (v11.y - v10.y);
            xo[3 + c] = a0 + wy * (a1 - a0);
        }
    }
}

// ---------------- kernel 3: persistent fused featbuild + tiled GEMM MLP ----------------
// Grid = 296 = 2 x 148 blocks (one exact wave at 2 blocks/SM). Each block loops
// tiles tile = bid, bid+296, ... < 1020. Weight prep ONCE per block.
// smem layout (bytes):
//   x_s   [24][260] f  @ 0       (24960)   (reused as layer-3 reduction buffer)
//   h_s   [48][260] f  @ 24960   (49920)
//   w1d   [24][48] ull @ 74880   (9216)
//   w2d   [48][48] ull @ 84096   (18432)
//   w3d   [3][48]  ull @ 102528  (1152)
//   b1d   [48]     ull @ 103680  (384)
//   b2d   [48]     ull @ 104064  (384)
#define GEMM_SMEM 104448
#define XS_STRIDE 260
#define GEMM_GRID 296
#define NTILES (G0 * BB)

__global__ __launch_bounds__(256, 2) void gemm_kernel(
    const float* __restrict__ w1, const float* __restrict__ g1, const float* __restrict__ b1,
    const float* __restrict__ rm1, const float* __restrict__ rv1,
    const float* __restrict__ w2, const float* __restrict__ g2, const float* __restrict__ b2,
    const float* __restrict__ rm2, const float* __restrict__ rv2,
    const float* __restrict__ w3) {

    extern __shared__ __align__(16) char smem_raw[];
    float* x_s = (float*)smem_raw;
    float* h_s = (float*)(smem_raw + 24960);
    ull* w1d = (ull*)(smem_raw + 74880);
    ull* w2d = (ull*)(smem_raw + 84096);
    ull* w3d = (ull*)(smem_raw + 102528);
    ull* b1d = (ull*)(smem_raw + 103680);
    ull* b2d = (ull*)(smem_raw + 104064);

    const int t = threadIdx.x;
    const int warp = t >> 5;
    const int lane = t & 31;
    const int o0   = warp * 6;          // 6 outputs per warp, uniform across lanes

    // ---- weight prep (folded BN, duplicated), ONCE per block ----
    for (int e = t; e < 48 * 24; e += 256) {
        int o = e / 24, c = e - o * 24;
        float inv1 = g1[o] * rsqrtf(rv1[o] + 1e-5f);
        float w = w1[e] * inv1;
        w1d[c * 48 + o] = pack2(w, w);
    }
    for (int e = t; e < 48 * 48; e += 256) {
        int o = e / 48, c = e - o * 48;
        float inv2 = g2[o] * rsqrtf(rv2[o] + 1e-5f);
        float w = w2[e] * inv2;
        w2d[c * 48 + o] = pack2(w, w);
    }
    if (t < 48) {
        float inv1 = g1[t] * rsqrtf(rv1[t] + 1e-5f);
        float bb1 = fmaf(-rm1[t], inv1, b1[t]);
        b1d[t] = pack2(bb1, bb1);
        float inv2 = g2[t] * rsqrtf(rv2[t] + 1e-5f);
        float bb2 = fmaf(-rm2[t], inv2, b2[t]);
        b2d[t] = pack2(bb2, bb2);
        #pragma unroll
        for (int cc = 0; cc < 3; ++cc) {
            float w = w3[cc * 48 + t];
            w3d[cc * 48 + t] = pack2(w, w);
        }
    }

    #pragma unroll 1
    for (int tile = blockIdx.x; tile < NTILES; tile += GEMM_GRID) {
        const int b = tile / G0;
        const int i = tile - b * G0;

        __syncthreads();   // previous tile's red reads done (and weight prep first time)

        // ---- feature build: thread t = pixel (i, j=t) ----
        {
            float x[24];
            if (t < 255) {
                const int j = t;
                #pragma unroll
                for (int c = 0; c < 3; ++c) {
                    int off = (b * 3 + c) * G0 * G0 + i * G0 + j;
                    float4 sv = dS4[off];              // one LDG.128
                    float sg  = sv.x * (1.f/64.f);
                    float ss  = sv.y * (1.f/64.f);
                    float sgg = sv.z * (1.f/64.f);
                    float sgs = sv.w * (1.f/64.f);
                    x[c]     = fmaf(-sg, ss, sgs);
                    x[3 + c] = fmaf(-sg, sg, sgg);
                }
                sampleLevel2(dF1v, G1, b, i, j, &x[6]);
                sampleLevel2(dF2v, G2, b, i, j, &x[12]);
                sampleLevel2(dF3v, G3, b, i, j, &x[18]);
            } else {
                #pragma unroll
                for (int f = 0; f < 24; ++f) x[f] = 0.f;
            }
            #pragma unroll
            for (int f = 0; f < 24; ++f)
                x_s[f * XS_STRIDE + t] = x[f];
        }
        __syncthreads();

        // lane owns pairs {2l, 2l+1, 2l+64, 2l+65}

        // ---- layer 1: 24 -> 48 ----
        ull acc[24];
        #pragma unroll
        for (int k = 0; k < 6; ++k) {
            ull bias = b1d[o0 + k];
            acc[k*4+0] = bias; acc[k*4+1] = bias; acc[k*4+2] = bias; acc[k*4+3] = bias;
        }
        #pragma unroll
        for (int c = 0; c < 24; ++c) {
            const float* xr = &x_s[c * XS_STRIDE];
            ulonglong2 xa = *(const ulonglong2*)(xr + 4 * lane);
            ulonglong2 xb = *(const ulonglong2*)(xr + 4 * lane + 128);
            const ulonglong2* wr = (const ulonglong2*)&w1d[c * 48 + o0];
            ulonglong2 w01 = wr[0], w23 = wr[1], w45 = wr[2];
            ull wv[6] = {w01.x, w01.y, w23.x, w23.y, w45.x, w45.y};
            #pragma unroll
            for (int k = 0; k < 6; ++k) {
                acc[k*4+0] = fma2(wv[k], xa.x, acc[k*4+0]);
                acc[k*4+1] = fma2(wv[k], xa.y, acc[k*4+1]);
                acc[k*4+2] = fma2(wv[k], xb.x, acc[k*4+2]);
                acc[k*4+3] = fma2(wv[k], xb.y, acc[k*4+3]);
            }
        }
        #pragma unroll
        for (int k = 0; k < 6; ++k) {
            float* hr = &h_s[(o0 + k) * XS_STRIDE];
            ulonglong2 v0; v0.x = relu2(acc[k*4+0]); v0.y = relu2(acc[k*4+1]);
            ulonglong2 v1; v1.x = relu2(acc[k*4+2]); v1.y = relu2(acc[k*4+3]);
            *(ulonglong2*)(hr + 4 * lane)       = v0;
            *(ulonglong2*)(hr + 4 * lane + 128) = v1;
        }
        __syncthreads();

        // ---- layer 2: 48 -> 48 ----
        #pragma unroll
        for (int k = 0; k < 6; ++k) {
            ull bias = b2d[o0 + k];
            acc[k*4+0] = bias; acc[k*4+1] = bias; acc[k*4+2] = bias; acc[k*4+3] = bias;
        }
        #pragma unroll
        for (int c = 0; c < 48; ++c) {
            const float* xr = &h_s[c * XS_STRIDE];
            ulonglong2 xa = *(const ulonglong2*)(xr + 4 * lane);
            ulonglong2 xb = *(const ulonglong2*)(xr + 4 * lane + 128);
            const ulonglong2* wr = (const ulonglong2*)&w2d[c * 48 + o0];
            ulonglong2 w01 = wr[0], w23 = wr[1], w45 = wr[2];
            ull wv[6] = {w01.x, w01.y, w23.x, w23.y, w45.x, w45.y};
            #pragma unroll
            for (int k = 0; k < 6; ++k) {
                acc[k*4+0] = fma2(wv[k], xa.x, acc[k*4+0]);
                acc[k*4+1] = fma2(wv[k], xa.y, acc[k*4+1]);
                acc[k*4+2] = fma2(wv[k], xb.x, acc[k*4+2]);
                acc[k*4+3] = fma2(wv[k], xb.y, acc[k*4+3]);
            }
        }
        // ---- layer 3 folded ----
        ull a3[12];
        #pragma unroll
        for (int m = 0; m < 12; ++m) a3[m] = 0ull;
        #pragma unroll
        for (int k = 0; k < 6; ++k) {
            ull r0 = relu2(acc[k*4+0]);
            ull r1 = relu2(acc[k*4+1]);
            ull r2 = relu2(acc[k*4+2]);
            ull r3 = relu2(acc[k*4+3]);
            #pragma unroll
            for (int cc = 0; cc < 3; ++cc) {
                ull w = w3d[cc * 48 + o0 + k];
                a3[cc*4+0] = fma2(w, r0, a3[cc*4+0]);
                a3[cc*4+1] = fma2(w, r1, a3[cc*4+1]);
                a3[cc*4+2] = fma2(w, r2, a3[cc*4+2]);
                a3[cc*4+3] = fma2(w, r3, a3[cc*4+3]);
            }
        }

        // ---- cross-warp reduction via smem (reuse x_s) ----
        ull* red = (ull*)x_s;
        {
            ull* rw = red + warp * 384;
            #pragma unroll
            for (int cc = 0; cc < 3; ++cc) {
                ulonglong2 v0; v0.x = a3[cc*4+0]; v0.y = a3[cc*4+1];
                ulonglong2 v1; v1.x = a3[cc*4+2]; v1.y = a3[cc*4+3];
                *(ulonglong2*)&rw[cc * 128 + 2 * lane]      = v0;
                *(ulonglong2*)&rw[cc * 128 + 2 * lane + 64] = v1;
            }
        }
        __syncthreads();

        for (int item = t; item < 384; item += 256) {
            int cc = item >> 7;
            int p  = item & 127;
            ull s = red[item];
            #pragma unroll
            for (int w = 1; w < 8; ++w) s = add2(s, red[w * 384 + item]);
            float2 A = unpack2(s);
            int plane = (b * 3 + cc) * G0 * G0 + i * G0;
            int j0 = 2 * p;
            {
                float4 sv = dS4[plane + j0];
                float mx = sv.x * (1.f/64.f);
                float my = sv.y * (1.f/64.f);
                dAf[plane + j0] = A.x;
                dCf[plane + j0] = fmaf(-A.x, mx, my);
            }
            if (j0 + 1 < G0) {
                float4 sv = dS4[plane + j0 + 1];
                float mx = sv.x * (1.f/64.f);
                float my = sv.y * (1.f/64.f);
                dAf[plane + j0 + 1] = A.y;
                dCf[plane + j0 + 1] = fmaf(-A.y, mx, my);
            }
        }
    }
}

// ---------------- kernel 4: upsample A,b + affine (simple 1-row) ----------------
__global__ __launch_bounds__(256) void final_kernel(const float* __restrict__ guide,
                                                    float* __restrict__ out) {
    __shared__ float sA[256];
    __shared__ float sC[256];
    const int y  = blockIdx.x;
    const int bc = blockIdx.y;
    const int t  = threadIdx.x;
    const float scale = (float)(254.0 / 1023.0);

    float py = y * scale;
    int iy = (int)py; if (iy > 253) iy = 253;
    float wy = py - iy;

    if (t < 255) {
        int b0 = bc * G0 * G0 + iy * G0 + t;
        float a0 = dAf[b0], a1 = dAf[b0 + G0];
        sA[t] = a0 + wy * (a1 - a0);
        float c0 = dCf[b0], c1 = dCf[b0 + G0];
        sC[t] = c0 + wy * (c1 - c0);
    }
    __syncthreads();

    size_t rowoff = ((size_t)bc * HH + y) * WW;
    float4 g = ((const float4*)(guide + rowoff))[t];
    float gv[4] = {g.x, g.y, g.z, g.w};
    float rv[4];
    #pragma unroll
    for (int k = 0; k < 4; ++k) {
        int xpix = 4 * t + k;
        float px = xpix * scale;
        int ix = (int)px; if (ix > 253) ix = 253;
        float wx = px - ix;
        float Av = sA[ix] + wx * (sA[ix + 1] - sA[ix]);
        float Cv = sC[ix] + wx * (sC[ix + 1] - sC[ix]);
        rv[k] = fmaf(Av, gv[k], Cv);
    }
    float4 r = {rv[0], rv[1], rv[2], rv[3]};
    ((float4*)(out + rowoff))[t] = r;
}

// ---------------- launch ----------------
extern "C" void kernel_launch(void* const* d_in, const int* in_sizes, int n_in,
                              void* d_out, int out_size) {
    const float* guide = (const float*)d_in[0];
    const float* src   = (const float*)d_in[1];
    const float* w1  = (const float*)d_in[2];
    const float* g1  = (const float*)d_in[3];
    const float* b1  = (const float*)d_in[4];
    const float* rm1 = (const float*)d_in[5];
    const float* rv1 = (const float*)d_in[6];
    const float* w2  = (const float*)d_in[7];
    const float* g2  = (const float*)d_in[8];
    const float* b2  = (const float*)d_in[9];
    const float* rm2 = (const float*)d_in[10];
    const float* rv2 = (const float*)d_in[11];
    const float* w3  = (const float*)d_in[12];
    float* out = (float*)d_out;

    cudaFuncSetAttribute(boxsum_kernel, cudaFuncAttributeMaxDynamicSharedMemorySize, 65536);
    cudaFuncSetAttribute(gemm_kernel, cudaFuncAttributeMaxDynamicSharedMemorySize, GEMM_SMEM);

    boxsum_kernel<<<dim3(32, NBC), 256, 65536>>>(guide, src);
    pyr_all_kernel<<<dim3((NPYR + 255) / 256, NBC), 256>>>();
    gemm_kernel<<<GEMM_GRID, 256, GEMM_SMEM>>>(w1, g1, b1, rm1, rv1, w2, g2, b2, rm2, rv2, w3);
    final_kernel<<<dim3(HH, NBC), 256>>>(guide, out);
}

// round 17
// speedup vs baseline: 1.5363x; 1.0111x over previous
#include <cuda_runtime.h>
#include <math.h>

#define BB 4
#define CC 3
#define HH 1024
#define WW 1024
#define NBC 12          // B*C
#define G0 255
#define G1 127
#define G2 63
#define G3 31

typedef unsigned long long ull;

// ---------------- f32x2 helpers ----------------
__device__ __forceinline__ ull pack2(float lo, float hi) {
    ull r; asm("mov.b64 %0, {%1,%2};" : "=l"(r) : "f"(lo), "f"(hi)); return r;
}
__device__ __forceinline__ float2 unpack2(ull v) {
    float2 r; asm("mov.b64 {%0,%1}, %2;" : "=f"(r.x), "=f"(r.y) : "l"(v)); return r;
}
__device__ __forceinline__ ull fma2(ull a, ull b, ull c) {
    ull d; asm("fma.rn.f32x2 %0, %1, %2, %3;" : "=l"(d) : "l"(a), "l"(b), "l"(c)); return d;
}
__device__ __forceinline__ ull add2(ull a, ull b) {
    ull d; asm("add.rn.f32x2 %0, %1, %2;" : "=l"(d) : "l"(a), "l"(b)); return d;
}
__device__ __forceinline__ ull relu2(ull v) {
    float2 t = unpack2(v);
    return pack2(fmaxf(t.x, 0.f), fmaxf(t.y, 0.f));
}
__device__ __forceinline__ void cpa16(void* smem, const void* g) {
    unsigned int a = (unsigned int)__cvta_generic_to_shared(smem);
    asm volatile("cp.async.cg.shared.global [%0], [%1], 16;" :: "r"(a), "l"(g));
}

// ---------------- scratch ----------------
__device__ __align__(16) float4 dS4[NBC*G0*G0];   // (Sg, Ss, Sgg, Sgs) per level-0 cell
__device__ __align__(8)  float2 dF1v[NBC*G1*G1];  // (cov, var) r=16
__device__ __align__(8)  float2 dF2v[NBC*G2*G2];  // r=32
__device__ __align__(8)  float2 dF3v[NBC*G3*G3];  // r=64
__device__ float dAf[NBC*G0*G0];                  // A
__device__ float dCf[NBC*G0*G0];                  // b = my1 - A*mx1

// ---------------- kernel 1: level-0 box sums, cp.async double-buffered ----------------
__global__ __launch_bounds__(256) void boxsum_kernel(const float* __restrict__ guide,
                                                     const float* __restrict__ src) {
    extern __shared__ __align__(16) float dyn[];
    float* bg[2] = {dyn, dyn + 4096};
    float* bs[2] = {dyn + 8192, dyn + 12288};

    const int t  = threadIdx.x;
    const int bc = blockIdx.y;
    const int i0 = blockIdx.x * 8;
    const int i1 = min(i0 + 8, 255);

    const float* gbase = guide + (size_t)bc * HH * WW;
    const float* sbase = src   + (size_t)bc * HH * WW;

    {
        const float* gp = gbase + (size_t)(4 * i0) * WW;
        const float* sp = sbase + (size_t)(4 * i0) * WW;
        #pragma unroll
        for (int k = 0; k < 4; ++k) {
            int idx = (t + k * 256) * 4;
            cpa16(bg[0] + idx, gp + idx);
            cpa16(bs[0] + idx, sp + idx);
        }
        asm volatile("cp.async.commit_group;");
    }

    float qg = 0.f, qs = 0.f, qgg = 0.f, qgs = 0.f;
    int s = 0;

    for (int m = i0; m <= i1; ++m) {
        if (m < i1) {
            const float* gp = gbase + (size_t)(4 * (m + 1)) * WW;
            const float* sp = sbase + (size_t)(4 * (m + 1)) * WW;
            #pragma unroll
            for (int k = 0; k < 4; ++k) {
                int idx = (t + k * 256) * 4;
                cpa16(bg[s ^ 1] + idx, gp + idx);
                cpa16(bs[s ^ 1] + idx, sp + idx);
            }
            asm volatile("cp.async.commit_group;");
            asm volatile("cp.async.wait_group 1;");
        } else {
            asm volatile("cp.async.wait_group 0;");
        }
        __syncthreads();

        if (t < 255) {
            float pg = 0.f, ps = 0.f, pgg = 0.f, pgs = 0.f;
            #pragma unroll
            for (int rr = 0; rr < 4; ++rr) {
                const float* g = bg[s] + rr * 1024 + 4 * t;
                const float* ss2 = bs[s] + rr * 1024 + 4 * t;
                float4 ga = *(const float4*)(g);
                float4 gb = *(const float4*)(g + 4);
                float4 sa = *(const float4*)(ss2);
                float4 sb = *(const float4*)(ss2 + 4);
                float gv[8] = {ga.x, ga.y, ga.z, ga.w, gb.x, gb.y, gb.z, gb.w};
                float sv[8] = {sa.x, sa.y, sa.z, sa.w, sb.x, sb.y, sb.z, sb.w};
                #pragma unroll
                for (int k = 0; k < 8; ++k) {
                    pg += gv[k];
                    ps += sv[k];
                    pgg = fmaf(gv[k], gv[k], pgg);
                    pgs = fmaf(gv[k], sv[k], pgs);
                }
            }
            if (m > i0) {
                int off = bc * G0 * G0 + (m - 1) * G0 + t;
                float4 v;
                v.x = qg + pg;
                v.y = qs + ps;
                v.z = qgg + pgg;
                v.w = qgs + pgs;
                dS4[off] = v;
            }
            qg = pg; qs = ps; qgg = pgg; qgs = pgs;
        }
        __syncthreads();
        s ^= 1;
    }
}

// ---------------- kernel 2: all pyramid levels directly from S0 ----------------
template<int T>
__device__ __forceinline__ void pyrL_direct(int bc, int i, int j, float INVN,
                                            float2* fcv, int GOUT) {
    int p00 = bc * G0 * G0 + (T * i) * G0 + (T * j);
    float sg = 0.f, ss = 0.f, sgg = 0.f, sgs = 0.f;
    #pragma unroll
    for (int a = 0; a < T; ++a) {
        const float4* r = &dS4[p00 + 2 * a * G0];
        #pragma unroll
        for (int bb2 = 0; bb2 < T; ++bb2) {
            float4 v = r[2 * bb2];
            sg += v.x; ss += v.y; sgg += v.z; sgs += v.w;
        }
    }
    float mx = sg * INVN, my = ss * INVN;
    int o = bc * GOUT * GOUT + i * GOUT + j;
    float cov = fmaf(-mx, my, sgs * INVN);
    float var = fmaf(-mx, mx, sgg * INVN);
    fcv[o] = make_float2(cov, var);
}

#define NL1 (G1*G1)
#define NL2 (G2*G2)
#define NL3 (G3*G3)
#define NPYR (NL1 + NL2 + NL3)

__global__ __launch_bounds__(256) void pyr_all_kernel() {
    const int bc  = blockIdx.y;
    int idx = blockIdx.x * 256 + threadIdx.x;
    if (idx < NL1) {
        int i = idx / G1, j = idx - i * G1;
        int p00 = bc * G0 * G0 + 2 * i * G0 + 2 * j;
        float4 v00 = dS4[p00],          v01 = dS4[p00 + 2];
        float4 v10 = dS4[p00 + 2 * G0], v11 = dS4[p00 + 2 * G0 + 2];
        float sg  = v00.x + v01.x + v10.x + v11.x;
        float ss  = v00.y + v01.y + v10.y + v11.y;
        float sgg = v00.z + v01.z + v10.z + v11.z;
        float sgs = v00.w + v01.w + v10.w + v11.w;
        float mx = sg * (1.f/256.f), my = ss * (1.f/256.f);
        int o = bc * G1 * G1 + idx;
        float cov = fmaf(-mx, my, sgs * (1.f/256.f));
        float var = fmaf(-mx, mx, sgg * (1.f/256.f));
        dF1v[o] = make_float2(cov, var);
    } else if (idx < NL1 + NL2) {
        int k = idx - NL1;
        int i = k / G2, j = k - i * G2;
        pyrL_direct<4>(bc, i, j, 1.f/1024.f, dF2v, G2);
    } else if (idx < NPYR) {
        int k = idx - NL1 - NL2;
        int i = k / G3, j = k - i * G3;
        pyrL_direct<8>(bc, i, j, 1.f/4096.f, dF3v, G3);
    }
}

// ---------------- bilinear over (cov,var) pairs ----------------
__device__ __forceinline__ void sampleLevel2(const float2* __restrict__ cvP,
                                             int G, int b, int i, int j, float* xo) {
    float scale = (float)((double)(G - 1) / 254.0);
    float py = i * scale, px = j * scale;
    int iy = (int)py; if (iy > G - 2) iy = G - 2;
    int ix = (int)px; if (ix > G - 2) ix = G - 2;
    float wy = py - iy, wx = px - ix;
    #pragma unroll
    for (int c = 0; c < 3; ++c) {
        int base = ((b * 3 + c) * G + iy) * G + ix;
        float2 v00 = cvP[base],     v01 = cvP[base + 1];
        float2 v10 = cvP[base + G], v11 = cvP[base + G + 1];
        {
            float a0 = v00.x + wx * (v01.x - v00.x);
            float a1 = v10.x + wx * (v11.x - v10.x);
            xo[c] = a0 + wy * (a1 - a0);
        }
        {
            float a0 = v00.y + wx * (v01.y - v00.y);
            float a1 = v10.y + wx * (v11.y - v10.y);
            xo[3 + c] = a0 + wy * (a1 - a0);
        }
    }
}

// ---------------- kernel 3: persistent fused featbuild + tiled GEMM MLP ----------------
#define GEMM_SMEM 104448
#define XS_STRIDE 260
#define GEMM_GRID 296
#define NTILES (G0 * BB)

__global__ __launch_bounds__(256, 2) void gemm_kernel(
    const float* __restrict__ w1, const float* __restrict__ g1, const float* __restrict__ b1,
    const float* __restrict__ rm1, const float* __restrict__ rv1,
    const float* __restrict__ w2, const float* __restrict__ g2, const float* __restrict__ b2,
    const float* __restrict__ rm2, const float* __restrict__ rv2,
    const float* __restrict__ w3) {

    extern __shared__ __align__(16) char smem_raw[];
    float* x_s = (float*)smem_raw;
    float* h_s = (float*)(smem_raw + 24960);
    ull* w1d = (ull*)(smem_raw + 74880);
    ull* w2d = (ull*)(smem_raw + 84096);
    ull* w3d = (ull*)(smem_raw + 102528);
    ull* b1d = (ull*)(smem_raw + 103680);
    ull* b2d = (ull*)(smem_raw + 104064);

    const int t = threadIdx.x;
    const int warp = t >> 5;
    const int lane = t & 31;
    const int o0   = warp * 6;          // 6 outputs per warp, uniform across lanes

    // ---- weight prep (folded BN, duplicated), ONCE per block ----
    for (int e = t; e < 48 * 24; e += 256) {
        int o = e / 24, c = e - o * 24;
        float inv1 = g1[o] * rsqrtf(rv1[o] + 1e-5f);
        float w = w1[e] * inv1;
        w1d[c * 48 + o] = pack2(w, w);
    }
    for (int e = t; e < 48 * 48; e += 256) {
        int o = e / 48, c = e - o * 48;
        float inv2 = g2[o] * rsqrtf(rv2[o] + 1e-5f);
        float w = w2[e] * inv2;
        w2d[c * 48 + o] = pack2(w, w);
    }
    if (t < 48) {
        float inv1 = g1[t] * rsqrtf(rv1[t] + 1e-5f);
        float bb1 = fmaf(-rm1[t], inv1, b1[t]);
        b1d[t] = pack2(bb1, bb1);
        float inv2 = g2[t] * rsqrtf(rv2[t] + 1e-5f);
        float bb2 = fmaf(-rm2[t], inv2, b2[t]);
        b2d[t] = pack2(bb2, bb2);
        #pragma unroll
        for (int cc = 0; cc < 3; ++cc) {
            float w = w3[cc * 48 + t];
            w3d[cc * 48 + t] = pack2(w, w);
        }
    }

    #pragma unroll 1
    for (int tile = blockIdx.x; tile < NTILES; tile += GEMM_GRID) {
        const int b = tile / G0;
        const int i = tile - b * G0;

        __syncthreads();   // previous tile's red reads done (and weight prep first time)

        // ---- feature build: thread t = pixel (i, j=t) ----
        {
            float x[24];
            if (t < 255) {
                const int j = t;
                #pragma unroll
                for (int c = 0; c < 3; ++c) {
                    int off = (b * 3 + c) * G0 * G0 + i * G0 + j;
                    float4 sv = dS4[off];
                    float sg  = sv.x * (1.f/64.f);
                    float ss  = sv.y * (1.f/64.f);
                    float sgg = sv.z * (1.f/64.f);
                    float sgs = sv.w * (1.f/64.f);
                    x[c]     = fmaf(-sg, ss, sgs);
                    x[3 + c] = fmaf(-sg, sg, sgg);
                }
                sampleLevel2(dF1v, G1, b, i, j, &x[6]);
                sampleLevel2(dF2v, G2, b, i, j, &x[12]);
                sampleLevel2(dF3v, G3, b, i, j, &x[18]);
            } else {
                #pragma unroll
                for (int f = 0; f < 24; ++f) x[f] = 0.f;
            }
            #pragma unroll
            for (int f = 0; f < 24; ++f)
                x_s[f * XS_STRIDE + t] = x[f];
        }
        __syncthreads();

        // lane owns pairs {2l, 2l+1, 2l+64, 2l+65}

        // ---- layer 1: 24 -> 48 ----
        ull acc[24];
        #pragma unroll
        for (int k = 0; k < 6; ++k) {
            ull bias = b1d[o0 + k];
            acc[k*4+0] = bias; acc[k*4+1] = bias; acc[k*4+2] = bias; acc[k*4+3] = bias;
        }
        #pragma unroll
        for (int c = 0; c < 24; ++c) {
            const float* xr = &x_s[c * XS_STRIDE];
            ulonglong2 xa = *(const ulonglong2*)(xr + 4 * lane);
            ulonglong2 xb = *(const ulonglong2*)(xr + 4 * lane + 128);
            const ulonglong2* wr = (const ulonglong2*)&w1d[c * 48 + o0];
            ulonglong2 w01 = wr[0], w23 = wr[1], w45 = wr[2];
            ull wv[6] = {w01.x, w01.y, w23.x, w23.y, w45.x, w45.y};
            #pragma unroll
            for (int k = 0; k < 6; ++k) {
                acc[k*4+0] = fma2(wv[k], xa.x, acc[k*4+0]);
                acc[k*4+1] = fma2(wv[k], xa.y, acc[k*4+1]);
                acc[k*4+2] = fma2(wv[k], xb.x, acc[k*4+2]);
                acc[k*4+3] = fma2(wv[k], xb.y, acc[k*4+3]);
            }
        }
        #pragma unroll
        for (int k = 0; k < 6; ++k) {
            float* hr = &h_s[(o0 + k) * XS_STRIDE];
            ulonglong2 v0; v0.x = relu2(acc[k*4+0]); v0.y = relu2(acc[k*4+1]);
            ulonglong2 v1; v1.x = relu2(acc[k*4+2]); v1.y = relu2(acc[k*4+3]);
            *(ulonglong2*)(hr + 4 * lane)       = v0;
            *(ulonglong2*)(hr + 4 * lane + 128) = v1;
        }
        __syncthreads();

        // ---- layer 2: 48 -> 48 ----
        #pragma unroll
        for (int k = 0; k < 6; ++k) {
            ull bias = b2d[o0 + k];
            acc[k*4+0] = bias; acc[k*4+1] = bias; acc[k*4+2] = bias; acc[k*4+3] = bias;
        }
        #pragma unroll
        for (int c = 0; c < 48; ++c) {
            const float* xr = &h_s[c * XS_STRIDE];
            ulonglong2 xa = *(const ulonglong2*)(xr + 4 * lane);
            ulonglong2 xb = *(const ulonglong2*)(xr + 4 * lane + 128);
            const ulonglong2* wr = (const ulonglong2*)&w2d[c * 48 + o0];
            ulonglong2 w01 = wr[0], w23 = wr[1], w45 = wr[2];
            ull wv[6] = {w01.x, w01.y, w23.x, w23.y, w45.x, w45.y};
            #pragma unroll
            for (int k = 0; k < 6; ++k) {
                acc[k*4+0] = fma2(wv[k], xa.x, acc[k*4+0]);
                acc[k*4+1] = fma2(wv[k], xa.y, acc[k*4+1]);
                acc[k*4+2] = fma2(wv[k], xb.x, acc[k*4+2]);
                acc[k*4+3] = fma2(wv[k], xb.y, acc[k*4+3]);
            }
        }
        // ---- layer 3 folded ----
        ull a3[12];
        #pragma unroll
        for (int m = 0; m < 12; ++m) a3[m] = 0ull;
        #pragma unroll
        for (int k = 0; k < 6; ++k) {
            ull r0 = relu2(acc[k*4+0]);
            ull r1 = relu2(acc[k*4+1]);
            ull r2 = relu2(acc[k*4+2]);
            ull r3 = relu2(acc[k*4+3]);
            #pragma unroll
            for (int cc = 0; cc < 3; ++cc) {
                ull w = w3d[cc * 48 + o0 + k];
                a3[cc*4+0] = fma2(w, r0, a3[cc*4+0]);
                a3[cc*4+1] = fma2(w, r1, a3[cc*4+1]);
                a3[cc*4+2] = fma2(w, r2, a3[cc*4+2]);
                a3[cc*4+3] = fma2(w, r3, a3[cc*4+3]);
            }
        }

        // ---- cross-warp reduction via smem (reuse x_s) ----
        ull* red = (ull*)x_s;
        {
            ull* rw = red + warp * 384;
            #pragma unroll
            for (int cc = 0; cc < 3; ++cc) {
                ulonglong2 v0; v0.x = a3[cc*4+0]; v0.y = a3[cc*4+1];
                ulonglong2 v1; v1.x = a3[cc*4+2]; v1.y = a3[cc*4+3];
                *(ulonglong2*)&rw[cc * 128 + 2 * lane]      = v0;
                *(ulonglong2*)&rw[cc * 128 + 2 * lane + 64] = v1;
            }
        }
        __syncthreads();

        for (int item = t; item < 384; item += 256) {
            int cc = item >> 7;
            int p  = item & 127;
            ull s = red[item];
            #pragma unroll
            for (int w = 1; w < 8; ++w) s = add2(s, red[w * 384 + item]);
            float2 A = unpack2(s);
            int plane = (b * 3 + cc) * G0 * G0 + i * G0;
            int j0 = 2 * p;
            {
                float4 sv = dS4[plane + j0];
                float mx = sv.x * (1.f/64.f);
                float my = sv.y * (1.f/64.f);
                dAf[plane + j0] = A.x;
                dCf[plane + j0] = fmaf(-A.x, mx, my);
            }
            if (j0 + 1 < G0) {
                float4 sv = dS4[plane + j0 + 1];
                float mx = sv.x * (1.f/64.f);
                float my = sv.y * (1.f/64.f);
                dAf[plane + j0 + 1] = A.y;
                dCf[plane + j0 + 1] = fmaf(-A.y, mx, my);
            }
        }
    }
}

// ---------------- kernel 4: upsample A,b + affine (fused float2 (A,C) table) ----------------
__global__ __launch_bounds__(256) void final_kernel(const float* __restrict__ guide,
                                                    float* __restrict__ out) {
    __shared__ __align__(8) float2 sAC[256];   // (Aval, Cval) per column knot
    const int y  = blockIdx.x;
    const int bc = blockIdx.y;
    const int t  = threadIdx.x;
    const float scale = (float)(254.0 / 1023.0);

    float py = y * scale;
    int iy = (int)py; if (iy > 253) iy = 253;
    float wy = py - iy;

    if (t < 255) {
        int b0 = bc * G0 * G0 + iy * G0 + t;
        float a0 = dAf[b0], a1 = dAf[b0 + G0];
        float c0 = dCf[b0], c1 = dCf[b0 + G0];
        sAC[t] = make_float2(a0 + wy * (a1 - a0), c0 + wy * (c1 - c0));
    }
    __syncthreads();

    size_t rowoff = ((size_t)bc * HH + y) * WW;
    float4 g = ((const float4*)(guide + rowoff))[t];
    float gv[4] = {g.x, g.y, g.z, g.w};
    float rv[4];
    #pragma unroll
    for (int k = 0; k < 4; ++k) {
        int xpix = 4 * t + k;
        float px = xpix * scale;
        int ix = (int)px; if (ix > 253) ix = 253;
        float wx = px - ix;
        float2 v0 = sAC[ix];        // LDS.64
        float2 v1 = sAC[ix + 1];    // LDS.64
        float Av = v0.x + wx * (v1.x - v0.x);
        float Cv = v0.y + wx * (v1.y - v0.y);
        rv[k] = fmaf(Av, gv[k], Cv);
    }
    float4 r = {rv[0], rv[1], rv[2], rv[3]};
    ((float4*)(out + rowoff))[t] = r;
}

// ---------------- launch ----------------
extern "C" void kernel_launch(void* const* d_in, const int* in_sizes, int n_in,
                              void* d_out, int out_size) {
    const float* guide = (const float*)d_in[0];
    const float* src   = (const float*)d_in[1];
    const float* w1  = (const float*)d_in[2];
    const float* g1  = (const float*)d_in[3];
    const float* b1  = (const float*)d_in[4];
    const float* rm1 = (const float*)d_in[5];
    const float* rv1 = (const float*)d_in[6];
    const float* w2  = (const float*)d_in[7];
    const float* g2  = (const float*)d_in[8];
    const float* b2  = (const float*)d_in[9];
    const float* rm2 = (const float*)d_in[10];
    const float* rv2 = (const float*)d_in[11];
    const float* w3  = (const float*)d_in[12];
    float* out = (float*)d_out;

    cudaFuncSetAttribute(boxsum_kernel, cudaFuncAttributeMaxDynamicSharedMemorySize, 65536);
    cudaFuncSetAttribute(gemm_kernel, cudaFuncAttributeMaxDynamicSharedMemorySize, GEMM_SMEM);

    boxsum_kernel<<<dim3(32, NBC), 256, 65536>>>(guide, src);
    pyr_all_kernel<<<dim3((NPYR + 255) / 256, NBC), 256>>>();
    gemm_kernel<<<GEMM_GRID, 256, GEMM_SMEM>>>(w1, g1, b1, rm1, rv1, w2, g2, b2, rm2, rv2, w3);
    final_kernel<<<dim3(HH, NBC), 256>>>(guide, out);
}